// round 1
// baseline (speedup 1.0000x reference)
#include <cuda_runtime.h>
#include <math.h>

#define B_ 8
#define N_ 2048
#define D_ 256
#define F_ 128
#define R_ 2
#define KQ 384            // D_+F_
#define M_TOT (B_*N_)     // 16384

// ---------------- scratch (static device globals; no allocation) ----------------
__device__ float g_x1[B_*F_];                       // (8,128)
__device__ float g_q [(size_t)M_TOT*D_];            // (B*N, D)
__device__ float g_k [(size_t)B_*R_*N_*D_];         // (B,R,N,D)
__device__ float g_v [(size_t)B_*R_*N_*D_];         // (B,R,N,D)
__device__ float g_s [(size_t)B_*R_*N_*N_];         // (B,R,N,N) scores/probs 256MB
__device__ float g_h [(size_t)M_TOT*R_*D_];         // (B*N, R*D) h_concat

// ---------------- x1 = input_x @ WQi_w + WQi_b ----------------
__global__ void k_x1(const float* __restrict__ input_x,
                     const float* __restrict__ Ww,
                     const float* __restrict__ Wb) {
    __shared__ float row[F_];
    int b = blockIdx.x, j = threadIdx.x;
    row[j] = input_x[b*F_ + j];
    __syncthreads();
    float s = Wb[j];
    #pragma unroll 4
    for (int c = 0; c < F_; c++) s = fmaf(row[c], Ww[c*F_ + j], s);
    g_x1[b*F_ + j] = s;
}

// ---------------- q,k,v GEMM: [concat(node_embed,x1)] (16384x384) @ W (384x1280) ----
__global__ void k_qkv(const float* __restrict__ node_embed,
                      const float* __restrict__ WQ_w, const float* __restrict__ WQ_b,
                      const float* __restrict__ WK_w, const float* __restrict__ WK_b,
                      const float* __restrict__ WV_w, const float* __restrict__ WV_b) {
    __shared__ float As[16][132];
    __shared__ float Bs[16][132];
    int tid = threadIdx.x;
    int tx = tid & 15, ty = tid >> 4;
    int bm = blockIdx.y, bn = blockIdx.x;           // bn in [0,10)
    int m0 = bm * 128;
    int chunk = bn >> 1;                            // 0:q 1,2:k 3,4:v
    int j0 = (bn & 1) * 128;

    const float* Wbase; const float* bias;
    if (chunk == 0)      { Wbase = WQ_w;                          bias = WQ_b; }
    else if (chunk <= 2) { Wbase = WK_w + (size_t)(chunk-1)*KQ*D_; bias = WK_b + (chunk-1)*D_; }
    else                 { Wbase = WV_w + (size_t)(chunk-3)*KQ*D_; bias = WV_b + (chunk-3)*D_; }

    float acc[8][8];
    #pragma unroll
    for (int i = 0; i < 8; i++)
        #pragma unroll
        for (int j = 0; j < 8; j++) acc[i][j] = 0.f;

    int la_k = (tid & 3) * 4;    // k offset 0..12
    int la_m = tid >> 2;         // 0..63
    int lb_j = (tid & 31) * 4;   // 0..124
    int lb_c = tid >> 5;         // 0..7

    for (int c0 = 0; c0 < KQ; c0 += 16) {
        #pragma unroll
        for (int p2 = 0; p2 < 2; p2++) {
            int m = m0 + la_m + p2*64;
            int c = c0 + la_k;
            float4 a;
            if (c < D_) a = *(const float4*)(node_embed + (size_t)m*D_ + c);
            else        a = *(const float4*)(g_x1 + (size_t)(m >> 11)*F_ + (c - D_));
            As[la_k+0][la_m + p2*64] = a.x;
            As[la_k+1][la_m + p2*64] = a.y;
            As[la_k+2][la_m + p2*64] = a.z;
            As[la_k+3][la_m + p2*64] = a.w;
        }
        #pragma unroll
        for (int p2 = 0; p2 < 2; p2++) {
            int c = c0 + lb_c + p2*8;
            float4 wv = *(const float4*)(Wbase + (size_t)c*D_ + j0 + lb_j);
            *(float4*)&Bs[lb_c + p2*8][lb_j] = wv;
        }
        __syncthreads();
        #pragma unroll
        for (int kk = 0; kk < 16; kk++) {
            float ra[8], rb[8];
            *(float4*)(ra  ) = *(const float4*)&As[kk][ty*8];
            *(float4*)(ra+4) = *(const float4*)&As[kk][ty*8+4];
            *(float4*)(rb  ) = *(const float4*)&Bs[kk][tx*8];
            *(float4*)(rb+4) = *(const float4*)&Bs[kk][tx*8+4];
            #pragma unroll
            for (int i = 0; i < 8; i++)
                #pragma unroll
                for (int j = 0; j < 8; j++)
                    acc[i][j] = fmaf(ra[i], rb[j], acc[i][j]);
        }
        __syncthreads();
    }

    float bv[8];
    #pragma unroll
    for (int uj = 0; uj < 8; uj++) bv[uj] = bias[j0 + tx*8 + uj];

    #pragma unroll
    for (int ui = 0; ui < 8; ui++) {
        int i = m0 + ty*8 + ui;
        int bb = i >> 11, n = i & (N_-1);
        float* outp;
        if (chunk == 0)      outp = g_q + (size_t)i*D_ + j0 + tx*8;
        else if (chunk <= 2) outp = g_k + ((size_t)(bb*R_ + (chunk-1))*N_ + n)*D_ + j0 + tx*8;
        else                 outp = g_v + ((size_t)(bb*R_ + (chunk-3))*N_ + n)*D_ + j0 + tx*8;
        float4 w0 = make_float4(acc[ui][0]+bv[0], acc[ui][1]+bv[1], acc[ui][2]+bv[2], acc[ui][3]+bv[3]);
        float4 w1 = make_float4(acc[ui][4]+bv[4], acc[ui][5]+bv[5], acc[ui][6]+bv[6], acc[ui][7]+bv[7]);
        *(float4*)(outp)   = w0;
        *(float4*)(outp+4) = w1;
    }
}

// ---------------- scores = q @ k^T / 16, masked by adj ----------------
__global__ void k_scores(const int* __restrict__ adj) {
    __shared__ float As[16][132];
    __shared__ float Bs[16][132];
    int tid = threadIdx.x;
    int tx = tid & 15, ty = tid >> 4;
    int p  = blockIdx.z;                     // b*2+r
    int m0 = blockIdx.y * 128, n0 = blockIdx.x * 128;
    const float* Aq = g_q + (size_t)(p >> 1)*N_*D_;
    const float* Bk = g_k + (size_t)p*N_*D_;

    float acc[8][8];
    #pragma unroll
    for (int i = 0; i < 8; i++)
        #pragma unroll
        for (int j = 0; j < 8; j++) acc[i][j] = 0.f;

    int la_k = (tid & 3) * 4;
    int la_m = tid >> 2;

    for (int c0 = 0; c0 < D_; c0 += 16) {
        #pragma unroll
        for (int p2 = 0; p2 < 2; p2++) {
            int m = m0 + la_m + p2*64;
            float4 a = *(const float4*)(Aq + (size_t)m*D_ + c0 + la_k);
            As[la_k+0][la_m + p2*64] = a.x;
            As[la_k+1][la_m + p2*64] = a.y;
            As[la_k+2][la_m + p2*64] = a.z;
            As[la_k+3][la_m + p2*64] = a.w;
            int n = n0 + la_m + p2*64;
            float4 bq = *(const float4*)(Bk + (size_t)n*D_ + c0 + la_k);
            Bs[la_k+0][la_m + p2*64] = bq.x;
            Bs[la_k+1][la_m + p2*64] = bq.y;
            Bs[la_k+2][la_m + p2*64] = bq.z;
            Bs[la_k+3][la_m + p2*64] = bq.w;
        }
        __syncthreads();
        #pragma unroll
        for (int kk = 0; kk < 16; kk++) {
            float ra[8], rb[8];
            *(float4*)(ra  ) = *(const float4*)&As[kk][ty*8];
            *(float4*)(ra+4) = *(const float4*)&As[kk][ty*8+4];
            *(float4*)(rb  ) = *(const float4*)&Bs[kk][tx*8];
            *(float4*)(rb+4) = *(const float4*)&Bs[kk][tx*8+4];
            #pragma unroll
            for (int i = 0; i < 8; i++)
                #pragma unroll
                for (int j = 0; j < 8; j++)
                    acc[i][j] = fmaf(ra[i], rb[j], acc[i][j]);
        }
        __syncthreads();
    }

    const int* adjp = adj + (size_t)p*N_*N_;
    float*     outp = g_s + (size_t)p*N_*N_;
    #pragma unroll
    for (int ui = 0; ui < 8; ui++) {
        int i = m0 + ty*8 + ui;
        size_t base = (size_t)i*N_ + n0 + tx*8;
        int4 a0 = *(const int4*)(adjp + base);
        int4 a1 = *(const int4*)(adjp + base + 4);
        float4 w0, w1;
        w0.x = a0.x ? acc[ui][0]*0.0625f : -1e9f;
        w0.y = a0.y ? acc[ui][1]*0.0625f : -1e9f;
        w0.z = a0.z ? acc[ui][2]*0.0625f : -1e9f;
        w0.w = a0.w ? acc[ui][3]*0.0625f : -1e9f;
        w1.x = a1.x ? acc[ui][4]*0.0625f : -1e9f;
        w1.y = a1.y ? acc[ui][5]*0.0625f : -1e9f;
        w1.z = a1.z ? acc[ui][6]*0.0625f : -1e9f;
        w1.w = a1.w ? acc[ui][7]*0.0625f : -1e9f;
        *(float4*)(outp + base)     = w0;
        *(float4*)(outp + base + 4) = w1;
    }
}

// ---------------- row softmax over N=2048 ----------------
__global__ void k_softmax() {
    size_t row = blockIdx.x;
    float* sp = g_s + row * (size_t)N_;
    int t = threadIdx.x;                 // 256 threads
    int lane = t & 31, warp = t >> 5;
    __shared__ float wred[8];
    __shared__ float bmax, bsum;

    float v[8];
    float m = -INFINITY;
    #pragma unroll
    for (int k2 = 0; k2 < 8; k2++) { v[k2] = sp[t + k2*256]; m = fmaxf(m, v[k2]); }
    #pragma unroll
    for (int o = 16; o; o >>= 1) m = fmaxf(m, __shfl_xor_sync(0xffffffffu, m, o));
    if (lane == 0) wred[warp] = m;
    __syncthreads();
    if (t == 0) {
        float mm = wred[0];
        #pragma unroll
        for (int i = 1; i < 8; i++) mm = fmaxf(mm, wred[i]);
        bmax = mm;
    }
    __syncthreads();
    m = bmax;
    float sum = 0.f;
    #pragma unroll
    for (int k2 = 0; k2 < 8; k2++) { v[k2] = __expf(v[k2] - m); sum += v[k2]; }
    #pragma unroll
    for (int o = 16; o; o >>= 1) sum += __shfl_xor_sync(0xffffffffu, sum, o);
    if (lane == 0) wred[warp] = sum;
    __syncthreads();
    if (t == 0) {
        float ss = 0.f;
        #pragma unroll
        for (int i = 0; i < 8; i++) ss += wred[i];
        bsum = ss;
    }
    __syncthreads();
    float inv = __fdividef(1.f, bsum);
    #pragma unroll
    for (int k2 = 0; k2 < 8; k2++) sp[t + k2*256] = v[k2] * inv;
}

// ---------------- m = alpha @ v  -> h_concat ----------------
__global__ void k_av() {
    __shared__ float As[16][132];
    __shared__ float Bs[16][132];
    int tid = threadIdx.x;
    int tx = tid & 15, ty = tid >> 4;
    int p  = blockIdx.z;
    int m0 = blockIdx.y * 128, n0 = blockIdx.x * 128;  // n0 in {0,128}
    const float* Ap = g_s + (size_t)p*N_*N_;
    const float* Vp = g_v + (size_t)p*N_*D_;

    float acc[8][8];
    #pragma unroll
    for (int i = 0; i < 8; i++)
        #pragma unroll
        for (int j = 0; j < 8; j++) acc[i][j] = 0.f;

    int la_k = (tid & 3) * 4;
    int la_m = tid >> 2;
    int lb_j = (tid & 31) * 4;
    int lb_c = tid >> 5;

    for (int c0 = 0; c0 < N_; c0 += 16) {
        #pragma unroll
        for (int p2 = 0; p2 < 2; p2++) {
            int m = m0 + la_m + p2*64;
            float4 a = *(const float4*)(Ap + (size_t)m*N_ + c0 + la_k);
            As[la_k+0][la_m + p2*64] = a.x;
            As[la_k+1][la_m + p2*64] = a.y;
            As[la_k+2][la_m + p2*64] = a.z;
            As[la_k+3][la_m + p2*64] = a.w;
        }
        #pragma unroll
        for (int p2 = 0; p2 < 2; p2++) {
            int c = c0 + lb_c + p2*8;
            float4 wv = *(const float4*)(Vp + (size_t)c*D_ + n0 + lb_j);
            *(float4*)&Bs[lb_c + p2*8][lb_j] = wv;
        }
        __syncthreads();
        #pragma unroll
        for (int kk = 0; kk < 16; kk++) {
            float ra[8], rb[8];
            *(float4*)(ra  ) = *(const float4*)&As[kk][ty*8];
            *(float4*)(ra+4) = *(const float4*)&As[kk][ty*8+4];
            *(float4*)(rb  ) = *(const float4*)&Bs[kk][tx*8];
            *(float4*)(rb+4) = *(const float4*)&Bs[kk][tx*8+4];
            #pragma unroll
            for (int i = 0; i < 8; i++)
                #pragma unroll
                for (int j = 0; j < 8; j++)
                    acc[i][j] = fmaf(ra[i], rb[j], acc[i][j]);
        }
        __syncthreads();
    }

    int b = p >> 1, r = p & 1;
    #pragma unroll
    for (int ui = 0; ui < 8; ui++) {
        int i = m0 + ty*8 + ui;
        float* op = g_h + ((size_t)(b*N_ + i))*(R_*D_) + r*D_ + n0 + tx*8;
        *(float4*)(op)   = make_float4(acc[ui][0], acc[ui][1], acc[ui][2], acc[ui][3]);
        *(float4*)(op+4) = make_float4(acc[ui][4], acc[ui][5], acc[ui][6], acc[ui][7]);
    }
}

// ---------------- h_fused GEMM + relu + residual + LayerNorm ----------------
__global__ void k_fused(const float* __restrict__ node_embed,
                        const float* __restrict__ WF_w, const float* __restrict__ WF_b,
                        const float* __restrict__ ln_g, const float* __restrict__ ln_b,
                        float* __restrict__ out) {
    __shared__ float As[16][68];
    __shared__ float Bs[16][260];
    int tid = threadIdx.x;
    int tx = tid & 31, ty = tid >> 5;     // cols tx*8 (256), rows ty*8 (64)
    int m0 = blockIdx.x * 64;

    float acc[8][8];
    #pragma unroll
    for (int i = 0; i < 8; i++)
        #pragma unroll
        for (int j = 0; j < 8; j++) acc[i][j] = 0.f;

    int la_k = (tid & 3) * 4;
    int la_m = tid >> 2;                  // 0..63
    int lb_j = (tid & 63) * 4;            // 0..252
    int lb_c = tid >> 6;                  // 0..3

    for (int c0 = 0; c0 < R_*D_; c0 += 16) {
        float4 a = *(const float4*)(g_h + (size_t)(m0 + la_m)*(R_*D_) + c0 + la_k);
        As[la_k+0][la_m] = a.x;
        As[la_k+1][la_m] = a.y;
        As[la_k+2][la_m] = a.z;
        As[la_k+3][la_m] = a.w;
        #pragma unroll
        for (int p2 = 0; p2 < 4; p2++) {
            int c = c0 + lb_c + p2*4;
            *(float4*)&Bs[lb_c + p2*4][lb_j] =
                *(const float4*)(WF_w + (size_t)c*D_ + lb_j);
        }
        __syncthreads();
        #pragma unroll
        for (int kk = 0; kk < 16; kk++) {
            float ra[8], rb[8];
            *(float4*)(ra  ) = *(const float4*)&As[kk][ty*8];
            *(float4*)(ra+4) = *(const float4*)&As[kk][ty*8+4];
            *(float4*)(rb  ) = *(const float4*)&Bs[kk][tx*8];
            *(float4*)(rb+4) = *(const float4*)&Bs[kk][tx*8+4];
            #pragma unroll
            for (int i = 0; i < 8; i++)
                #pragma unroll
                for (int j = 0; j < 8; j++)
                    acc[i][j] = fmaf(ra[i], rb[j], acc[i][j]);
        }
        __syncthreads();
    }

    float wb[8], g[8], bb2[8];
    #pragma unroll
    for (int uj = 0; uj < 8; uj++) {
        int j = tx*8 + uj;
        wb[uj] = WF_b[j]; g[uj] = ln_g[j]; bb2[uj] = ln_b[j];
    }

    // one warp (same ty) owns rows ty*8..ty*8+7 fully -> per-row warp LN
    #pragma unroll
    for (int ui = 0; ui < 8; ui++) {
        int i = m0 + ty*8 + ui;
        const float* ne = node_embed + (size_t)i*D_ + tx*8;
        float y[8];
        float s = 0.f;
        #pragma unroll
        for (int uj = 0; uj < 8; uj++) {
            float h = acc[ui][uj] + wb[uj];
            h = h > 0.f ? h : 0.f;
            float val = ne[uj] + h;
            y[uj] = val;
            s += val;
        }
        #pragma unroll
        for (int o = 16; o; o >>= 1) s += __shfl_xor_sync(0xffffffffu, s, o);
        float mu = s * (1.0f/256.0f);
        float sq = 0.f;
        #pragma unroll
        for (int uj = 0; uj < 8; uj++) { float d = y[uj] - mu; sq = fmaf(d, d, sq); }
        #pragma unroll
        for (int o = 16; o; o >>= 1) sq += __shfl_xor_sync(0xffffffffu, sq, o);
        float rstd = rsqrtf(sq * (1.0f/256.0f) + 1e-5f);
        float* op = out + (size_t)i*D_ + tx*8;
        #pragma unroll
        for (int uj = 0; uj < 8; uj++)
            op[uj] = (y[uj] - mu) * rstd * g[uj] + bb2[uj];
    }
}

// ---------------- launch ----------------
extern "C" void kernel_launch(void* const* d_in, const int* in_sizes, int n_in,
                              void* d_out, int out_size) {
    const float* node_embed = (const float*)d_in[0];
    const float* input_x    = (const float*)d_in[1];
    const int*   adj        = (const int*)  d_in[2];
    const float* WQi_w      = (const float*)d_in[3];
    const float* WQi_b      = (const float*)d_in[4];
    const float* WQ_w       = (const float*)d_in[5];
    const float* WQ_b       = (const float*)d_in[6];
    const float* WK_w       = (const float*)d_in[7];
    const float* WK_b       = (const float*)d_in[8];
    const float* WV_w       = (const float*)d_in[9];
    const float* WV_b       = (const float*)d_in[10];
    const float* WF_w       = (const float*)d_in[11];
    const float* WF_b       = (const float*)d_in[12];
    const float* ln_g       = (const float*)d_in[13];
    const float* ln_b       = (const float*)d_in[14];
    float* out = (float*)d_out;

    k_x1     <<<B_, F_>>>(input_x, WQi_w, WQi_b);
    k_qkv    <<<dim3(10, 128), 256>>>(node_embed, WQ_w, WQ_b, WK_w, WK_b, WV_w, WV_b);
    k_scores <<<dim3(16, 16, B_*R_), 256>>>(adj);
    k_softmax<<<B_*R_*N_, 256>>>();
    k_av     <<<dim3(2, 16, B_*R_), 256>>>();
    k_fused  <<<M_TOT/64, 256>>>(node_embed, WF_w, WF_b, ln_g, ln_b, out);
}

// round 3
// speedup vs baseline: 4.4645x; 4.4645x over previous
#include <cuda_runtime.h>
#include <cuda_bf16.h>
#include <math.h>

#define B_ 8
#define N_ 2048
#define D_ 256
#define F_ 128
#define R_ 2
#define KQ 384            // D_+F_
#define M_TOT (B_*N_)     // 16384

typedef __nv_bfloat16 bf16;
typedef __nv_bfloat162 bf162;

// ---------------- scratch ----------------
__device__ float g_x1[B_*F_];                            // (8,128) fp32
__device__ bf16  g_cat[(size_t)M_TOT*KQ];                // (16384,384)
__device__ bf16  g_q16[(size_t)M_TOT*D_];                // (16384,256)
__device__ bf16  g_k16[(size_t)B_*R_*N_*D_];             // (16,2048,256)
__device__ bf16  g_v16[(size_t)B_*R_*N_*D_];
__device__ bf16  g_s16[(size_t)B_*R_*N_*N_];             // scores/probs (16,2048,2048)
__device__ bf16  g_h16[(size_t)M_TOT*R_*D_];             // (16384,512)
__device__ bf16  g_wq16[KQ*D_];
__device__ bf16  g_wk16[R_*KQ*D_];
__device__ bf16  g_wv16[R_*KQ*D_];
__device__ bf16  g_wf16[R_*D_*D_];

// ---------------- PTX helpers ----------------
__device__ __forceinline__ unsigned smem_u32(const void* p) {
    return (unsigned)__cvta_generic_to_shared(p);
}
#define LDSM_X4(r0,r1,r2,r3,addr) \
    asm volatile("ldmatrix.sync.aligned.m8n8.x4.shared.b16 {%0,%1,%2,%3}, [%4];" \
        : "=r"(r0),"=r"(r1),"=r"(r2),"=r"(r3) : "r"(addr))
#define LDSM_X2(r0,r1,addr) \
    asm volatile("ldmatrix.sync.aligned.m8n8.x2.shared.b16 {%0,%1}, [%2];" \
        : "=r"(r0),"=r"(r1) : "r"(addr))
#define LDSM_X2T(r0,r1,addr) \
    asm volatile("ldmatrix.sync.aligned.m8n8.x2.trans.shared.b16 {%0,%1}, [%2];" \
        : "=r"(r0),"=r"(r1) : "r"(addr))
#define MMA16816(c,a0,a1,a2,a3,b0,b1) \
    asm volatile("mma.sync.aligned.m16n8k16.row.col.f32.bf16.bf16.f32 " \
        "{%0,%1,%2,%3},{%4,%5,%6,%7},{%8,%9},{%0,%1,%2,%3};" \
        : "+f"(c[0]),"+f"(c[1]),"+f"(c[2]),"+f"(c[3]) \
        : "r"(a0),"r"(a1),"r"(a2),"r"(a3),"r"(b0),"r"(b1))

// ---------------- x1 = input_x @ WQi_w + WQi_b (fp32, tiny) ----------------
__global__ void k_x1(const float* __restrict__ input_x,
                     const float* __restrict__ Ww,
                     const float* __restrict__ Wb) {
    __shared__ float row[F_];
    int b = blockIdx.x, j = threadIdx.x;
    row[j] = input_x[b*F_ + j];
    __syncthreads();
    float s = Wb[j];
    #pragma unroll 4
    for (int c = 0; c < F_; c++) s = fmaf(row[c], Ww[c*F_ + j], s);
    g_x1[b*F_ + j] = s;
}

// ---------------- build bf16 concat [node_embed | x1] ----------------
__global__ void k_cat(const float* __restrict__ node_embed) {
    int row = blockIdx.x;             // 16384
    int col2 = threadIdx.x * 2;       // 192 threads -> cols 0..382
    float2 v;
    if (col2 < D_) v = *(const float2*)(node_embed + (size_t)row*D_ + col2);
    else           v = *(const float2*)(g_x1 + (size_t)(row >> 11)*F_ + (col2 - D_));
    *(bf162*)(g_cat + (size_t)row*KQ + col2) = __float22bfloat162_rn(v);
}

// ---------------- convert weights to bf16 ----------------
__global__ void k_cvtw(const float* __restrict__ wq, const float* __restrict__ wk,
                       const float* __restrict__ wv, const float* __restrict__ wf) {
    int i = blockIdx.x * blockDim.x + threadIdx.x;
    int e = i * 2;
    const int SQ = KQ*D_, SK = R_*KQ*D_, SF = R_*D_*D_;
    if (e < SQ) {
        *(bf162*)(g_wq16 + e) = __float22bfloat162_rn(*(const float2*)(wq + e));
    } else if (e < SQ + SK) {
        int o = e - SQ;
        *(bf162*)(g_wk16 + o) = __float22bfloat162_rn(*(const float2*)(wk + o));
    } else if (e < SQ + 2*SK) {
        int o = e - SQ - SK;
        *(bf162*)(g_wv16 + o) = __float22bfloat162_rn(*(const float2*)(wv + o));
    } else if (e < SQ + 2*SK + SF) {
        int o = e - SQ - 2*SK;
        *(bf162*)(g_wf16 + o) = __float22bfloat162_rn(*(const float2*)(wf + o));
    }
}

// ============ qkv GEMM: g_cat (16384x384) @ W(384x1280) -> q16/k16/v16 ============
__global__ void __launch_bounds__(256) k_qkv16(
        const float* __restrict__ WQ_b, const float* __restrict__ WK_b,
        const float* __restrict__ WV_b) {
    __shared__ bf16 As[128*40];       // [m][k] pad 40
    __shared__ bf16 Bs[32*136];       // [k][n] pad 136
    int tid = threadIdx.x;
    int l = tid & 31, warp = tid >> 5;
    int warp_m = warp & 1, warp_n = warp >> 1;
    int quad = l >> 2, qlane = l & 3;

    int bn = blockIdx.x;              // 0..9
    int m0 = blockIdx.y * 128;
    int chunk = bn >> 1;
    int j0 = (bn & 1) * 128;

    const bf16* Wg; const float* bias;
    if (chunk == 0)      { Wg = g_wq16;                           bias = WQ_b; }
    else if (chunk <= 2) { Wg = g_wk16 + (size_t)(chunk-1)*KQ*D_; bias = WK_b + (chunk-1)*D_; }
    else                 { Wg = g_wv16 + (size_t)(chunk-3)*KQ*D_; bias = WV_b + (chunk-3)*D_; }

    float acc[4][4][4];
    #pragma unroll
    for (int i=0;i<4;i++) for (int j=0;j<4;j++) for (int c=0;c<4;c++) acc[i][j][c]=0.f;

    int a_row = tid >> 2, a_seg = tid & 3;            // +256: row+64
    int b_row = tid >> 4, b_seg = tid & 15;           // +256: row+16

    int arow = (l & 7) + ((l >> 3) & 1) * 8;
    int acol = (l >> 4) * 8;
    unsigned a_base = smem_u32(As) + (unsigned)(((warp_m*64 + arow)*40 + acol) * 2);
    int lt = l & 15;
    unsigned b_base = smem_u32(Bs) + (unsigned)((lt*136 + warp_n*32) * 2);

    {
        #pragma unroll
        for (int it=0; it<2; it++) {
            int r = a_row + it*64;
            *(uint4*)&As[r*40 + a_seg*8] =
                *(const uint4*)(g_cat + (size_t)(m0+r)*KQ + a_seg*8);
            int rb = b_row + it*16;
            *(uint4*)&Bs[rb*136 + b_seg*8] =
                *(const uint4*)(Wg + (size_t)rb*D_ + j0 + b_seg*8);
        }
    }
    __syncthreads();

    for (int c0 = 0; c0 < KQ; c0 += 32) {
        bool nxt = (c0 + 32 < KQ);
        uint4 pa0,pa1,pb0,pb1;
        if (nxt) {
            pa0 = *(const uint4*)(g_cat + (size_t)(m0+a_row   )*KQ + c0+32 + a_seg*8);
            pa1 = *(const uint4*)(g_cat + (size_t)(m0+a_row+64)*KQ + c0+32 + a_seg*8);
            pb0 = *(const uint4*)(Wg + (size_t)(c0+32+b_row   )*D_ + j0 + b_seg*8);
            pb1 = *(const uint4*)(Wg + (size_t)(c0+32+b_row+16)*D_ + j0 + b_seg*8);
        }
        #pragma unroll
        for (int ks = 0; ks < 2; ks++) {
            unsigned a0,a1,a2,a3;
            unsigned bfr[4][2];
            #pragma unroll
            for (int nt=0; nt<4; nt++) {
                unsigned addr = b_base + (unsigned)((ks*16*136 + nt*8) * 2);
                LDSM_X2T(bfr[nt][0], bfr[nt][1], addr);
            }
            #pragma unroll
            for (int mt=0; mt<4; mt++) {
                unsigned addr = a_base + (unsigned)((mt*16*40 + ks*16) * 2);
                LDSM_X4(a0,a1,a2,a3, addr);
                #pragma unroll
                for (int nt=0; nt<4; nt++)
                    MMA16816(acc[mt][nt], a0,a1,a2,a3, bfr[nt][0], bfr[nt][1]);
            }
        }
        __syncthreads();
        if (nxt) {
            *(uint4*)&As[(a_row   )*40 + a_seg*8] = pa0;
            *(uint4*)&As[(a_row+64)*40 + a_seg*8] = pa1;
            *(uint4*)&Bs[(b_row   )*136 + b_seg*8] = pb0;
            *(uint4*)&Bs[(b_row+16)*136 + b_seg*8] = pb1;
            __syncthreads();
        }
    }

    #pragma unroll
    for (int mt=0; mt<4; mt++) {
        #pragma unroll
        for (int half=0; half<2; half++) {
            int i = m0 + warp_m*64 + mt*16 + quad + half*8;
            int bb = i >> 11, ntok = i & (N_-1);
            #pragma unroll
            for (int nt=0; nt<4; nt++) {
                int jj = j0 + warp_n*32 + nt*8 + qlane*2;
                float2 bv = *(const float2*)(bias + jj);
                float v0 = acc[mt][nt][half*2+0] + bv.x;
                float v1 = acc[mt][nt][half*2+1] + bv.y;
                bf16* dst;
                if (chunk == 0)      dst = g_q16 + (size_t)i*D_ + jj;
                else if (chunk <= 2) dst = g_k16 + ((size_t)(bb*R_ + (chunk-1))*N_ + ntok)*D_ + jj;
                else                 dst = g_v16 + ((size_t)(bb*R_ + (chunk-3))*N_ + ntok)*D_ + jj;
                *(bf162*)dst = __float22bfloat162_rn(make_float2(v0, v1));
            }
        }
    }
}

// ============ scores = q @ k^T /16, masked -> bf16 ============
__global__ void __launch_bounds__(256) k_scores16(const int* __restrict__ adj) {
    __shared__ bf16 As[128*40];       // q [m][k]
    __shared__ bf16 Bs[128*40];       // k [n][k]
    int tid = threadIdx.x;
    int l = tid & 31, warp = tid >> 5;
    int warp_m = warp & 1, warp_n = warp >> 1;
    int quad = l >> 2, qlane = l & 3;

    int p  = blockIdx.z;
    int m0 = blockIdx.y * 128, n0 = blockIdx.x * 128;
    const bf16* Aq = g_q16 + (size_t)(p >> 1)*N_*D_;
    const bf16* Bk = g_k16 + (size_t)p*N_*D_;

    float acc[4][4][4];
    #pragma unroll
    for (int i=0;i<4;i++) for (int j=0;j<4;j++) for (int c=0;c<4;c++) acc[i][j][c]=0.f;

    int a_row = tid >> 2, a_seg = tid & 3;

    int arow = (l & 7) + ((l >> 3) & 1) * 8;
    int acol = (l >> 4) * 8;
    unsigned a_base = smem_u32(As) + (unsigned)(((warp_m*64 + arow)*40 + acol) * 2);
    int lt = l & 15;
    unsigned b_base = smem_u32(Bs) +
        (unsigned)(((warp_n*32 + (lt & 7))*40 + ((lt >> 3)*8)) * 2);

    {
        #pragma unroll
        for (int it=0; it<2; it++) {
            int r = a_row + it*64;
            *(uint4*)&As[r*40 + a_seg*8] = *(const uint4*)(Aq + (size_t)(m0+r)*D_ + a_seg*8);
            *(uint4*)&Bs[r*40 + a_seg*8] = *(const uint4*)(Bk + (size_t)(n0+r)*D_ + a_seg*8);
        }
    }
    __syncthreads();

    for (int c0 = 0; c0 < D_; c0 += 32) {
        bool nxt = (c0 + 32 < D_);
        uint4 pa0,pa1,pb0,pb1;
        if (nxt) {
            pa0 = *(const uint4*)(Aq + (size_t)(m0+a_row   )*D_ + c0+32 + a_seg*8);
            pa1 = *(const uint4*)(Aq + (size_t)(m0+a_row+64)*D_ + c0+32 + a_seg*8);
            pb0 = *(const uint4*)(Bk + (size_t)(n0+a_row   )*D_ + c0+32 + a_seg*8);
            pb1 = *(const uint4*)(Bk + (size_t)(n0+a_row+64)*D_ + c0+32 + a_seg*8);
        }
        #pragma unroll
        for (int ks = 0; ks < 2; ks++) {
            unsigned a0,a1,a2,a3;
            unsigned bfr[4][2];
            #pragma unroll
            for (int nt=0; nt<4; nt++) {
                unsigned addr = b_base + (unsigned)((nt*8*40 + ks*16) * 2);
                LDSM_X2(bfr[nt][0], bfr[nt][1], addr);
            }
            #pragma unroll
            for (int mt=0; mt<4; mt++) {
                unsigned addr = a_base + (unsigned)((mt*16*40 + ks*16) * 2);
                LDSM_X4(a0,a1,a2,a3, addr);
                #pragma unroll
                for (int nt=0; nt<4; nt++)
                    MMA16816(acc[mt][nt], a0,a1,a2,a3, bfr[nt][0], bfr[nt][1]);
            }
        }
        __syncthreads();
        if (nxt) {
            *(uint4*)&As[(a_row   )*40 + a_seg*8] = pa0;
            *(uint4*)&As[(a_row+64)*40 + a_seg*8] = pa1;
            *(uint4*)&Bs[(a_row   )*40 + a_seg*8] = pb0;
            *(uint4*)&Bs[(a_row+64)*40 + a_seg*8] = pb1;
            __syncthreads();
        }
    }

    const int* adjp = adj + (size_t)p*N_*N_;
    bf16* outp = g_s16 + (size_t)p*N_*N_;
    #pragma unroll
    for (int mt=0; mt<4; mt++) {
        #pragma unroll
        for (int half=0; half<2; half++) {
            int i = m0 + warp_m*64 + mt*16 + quad + half*8;
            #pragma unroll
            for (int nt=0; nt<4; nt++) {
                int j = n0 + warp_n*32 + nt*8 + qlane*2;
                int2 ad = *(const int2*)(adjp + (size_t)i*N_ + j);
                float v0 = ad.x ? acc[mt][nt][half*2+0]*0.0625f : -1e9f;
                float v1 = ad.y ? acc[mt][nt][half*2+1]*0.0625f : -1e9f;
                *(bf162*)(outp + (size_t)i*N_ + j) =
                    __float22bfloat162_rn(make_float2(v0, v1));
            }
        }
    }
}

// ---------------- row softmax (bf16 in-place) ----------------
__global__ void k_softmax() {
    size_t row = blockIdx.x;
    bf162* sp = reinterpret_cast<bf162*>(g_s16) + row * (N_/2);
    int t = threadIdx.x;                 // 256 threads, 4 bf162 each
    int lane = t & 31, warp = t >> 5;
    __shared__ float wred[8];
    __shared__ float bmax, bsum;

    float2 v[4];
    float m = -INFINITY;
    #pragma unroll
    for (int k2 = 0; k2 < 4; k2++) {
        v[k2] = __bfloat1622float2(sp[t + k2*256]);
        m = fmaxf(m, fmaxf(v[k2].x, v[k2].y));
    }
    #pragma unroll
    for (int o = 16; o; o >>= 1) m = fmaxf(m, __shfl_xor_sync(0xffffffffu, m, o));
    if (lane == 0) wred[warp] = m;
    __syncthreads();
    if (t == 0) {
        float mm = wred[0];
        #pragma unroll
        for (int i = 1; i < 8; i++) mm = fmaxf(mm, wred[i]);
        bmax = mm;
    }
    __syncthreads();
    m = bmax;
    float sum = 0.f;
    #pragma unroll
    for (int k2 = 0; k2 < 4; k2++) {
        v[k2].x = __expf(v[k2].x - m);
        v[k2].y = __expf(v[k2].y - m);
        sum += v[k2].x + v[k2].y;
    }
    #pragma unroll
    for (int o = 16; o; o >>= 1) sum += __shfl_xor_sync(0xffffffffu, sum, o);
    if (lane == 0) wred[warp] = sum;
    __syncthreads();
    if (t == 0) {
        float ss = 0.f;
        #pragma unroll
        for (int i = 0; i < 8; i++) ss += wred[i];
        bsum = ss;
    }
    __syncthreads();
    float inv = __fdividef(1.f, bsum);
    #pragma unroll
    for (int k2 = 0; k2 < 4; k2++)
        sp[t + k2*256] = __float22bfloat162_rn(make_float2(v[k2].x*inv, v[k2].y*inv));
}

// ============ m = alpha @ v -> h_concat bf16 ============
__global__ void __launch_bounds__(256) k_av16() {
    __shared__ bf16 As[128*40];       // probs [m][k]
    __shared__ bf16 Bs[32*136];       // v [k][n]
    int tid = threadIdx.x;
    int l = tid & 31, warp = tid >> 5;
    int warp_m = warp & 1, warp_n = warp >> 1;
    int quad = l >> 2, qlane = l & 3;

    int p  = blockIdx.z;
    int m0 = blockIdx.y * 128, n0 = blockIdx.x * 128;
    const bf16* Ap = g_s16 + (size_t)p*N_*N_;
    const bf16* Vp = g_v16 + (size_t)p*N_*D_;

    float acc[4][4][4];
    #pragma unroll
    for (int i=0;i<4;i++) for (int j=0;j<4;j++) for (int c=0;c<4;c++) acc[i][j][c]=0.f;

    int a_row = tid >> 2, a_seg = tid & 3;
    int b_row = tid >> 4, b_seg = tid & 15;

    int arow = (l & 7) + ((l >> 3) & 1) * 8;
    int acol = (l >> 4) * 8;
    unsigned a_base = smem_u32(As) + (unsigned)(((warp_m*64 + arow)*40 + acol) * 2);
    int lt = l & 15;
    unsigned b_base = smem_u32(Bs) + (unsigned)((lt*136 + warp_n*32) * 2);

    {
        #pragma unroll
        for (int it=0; it<2; it++) {
            int r = a_row + it*64;
            *(uint4*)&As[r*40 + a_seg*8] = *(const uint4*)(Ap + (size_t)(m0+r)*N_ + a_seg*8);
            int rb = b_row + it*16;
            *(uint4*)&Bs[rb*136 + b_seg*8] = *(const uint4*)(Vp + (size_t)rb*D_ + n0 + b_seg*8);
        }
    }
    __syncthreads();

    for (int c0 = 0; c0 < N_; c0 += 32) {
        bool nxt = (c0 + 32 < N_);
        uint4 pa0,pa1,pb0,pb1;
        if (nxt) {
            pa0 = *(const uint4*)(Ap + (size_t)(m0+a_row   )*N_ + c0+32 + a_seg*8);
            pa1 = *(const uint4*)(Ap + (size_t)(m0+a_row+64)*N_ + c0+32 + a_seg*8);
            pb0 = *(const uint4*)(Vp + (size_t)(c0+32+b_row   )*D_ + n0 + b_seg*8);
            pb1 = *(const uint4*)(Vp + (size_t)(c0+32+b_row+16)*D_ + n0 + b_seg*8);
        }
        #pragma unroll
        for (int ks = 0; ks < 2; ks++) {
            unsigned a0,a1,a2,a3;
            unsigned bfr[4][2];
            #pragma unroll
            for (int nt=0; nt<4; nt++) {
                unsigned addr = b_base + (unsigned)((ks*16*136 + nt*8) * 2);
                LDSM_X2T(bfr[nt][0], bfr[nt][1], addr);
            }
            #pragma unroll
            for (int mt=0; mt<4; mt++) {
                unsigned addr = a_base + (unsigned)((mt*16*40 + ks*16) * 2);
                LDSM_X4(a0,a1,a2,a3, addr);
                #pragma unroll
                for (int nt=0; nt<4; nt++)
                    MMA16816(acc[mt][nt], a0,a1,a2,a3, bfr[nt][0], bfr[nt][1]);
            }
        }
        __syncthreads();
        if (nxt) {
            *(uint4*)&As[(a_row   )*40 + a_seg*8] = pa0;
            *(uint4*)&As[(a_row+64)*40 + a_seg*8] = pa1;
            *(uint4*)&Bs[(b_row   )*136 + b_seg*8] = pb0;
            *(uint4*)&Bs[(b_row+16)*136 + b_seg*8] = pb1;
            __syncthreads();
        }
    }

    int b = p >> 1, r = p & 1;
    #pragma unroll
    for (int mt=0; mt<4; mt++) {
        #pragma unroll
        for (int half=0; half<2; half++) {
            int i = m0 + warp_m*64 + mt*16 + quad + half*8;
            #pragma unroll
            for (int nt=0; nt<4; nt++) {
                int j = n0 + warp_n*32 + nt*8 + qlane*2;
                float v0 = acc[mt][nt][half*2+0];
                float v1 = acc[mt][nt][half*2+1];
                *(bf162*)(g_h16 + ((size_t)(b*N_ + i))*(R_*D_) + r*D_ + j) =
                    __float22bfloat162_rn(make_float2(v0, v1));
            }
        }
    }
}

// ============ h_fused GEMM + relu + residual + LN (64m x 256n CTA) ============
__global__ void __launch_bounds__(256) k_fused16(
        const float* __restrict__ node_embed,
        const float* __restrict__ WF_b,
        const float* __restrict__ ln_g, const float* __restrict__ ln_b,
        float* __restrict__ out) {
    __shared__ bf16 As[64*40];        // h [m][k]
    __shared__ bf16 Bs[32*264];       // WF [k][n] pad 264
    __shared__ float2 part[64][4];
    int tid = threadIdx.x;
    int l = tid & 31, warp = tid >> 5;
    int warp_m = warp & 1, warp_n = warp >> 1;
    int quad = l >> 2, qlane = l & 3;
    int m0 = blockIdx.x * 64;

    float acc[2][8][4];
    #pragma unroll
    for (int i=0;i<2;i++) for (int j=0;j<8;j++) for (int c=0;c<4;c++) acc[i][j][c]=0.f;

    int a_row = tid >> 2, a_seg = tid & 3;     // 64 rows x 4 segs
    int b_row = tid >> 5, b_seg = tid & 31;    // 8 rows/iter x 32 segs

    int arow = (l & 7) + ((l >> 3) & 1) * 8;
    int acol = (l >> 4) * 8;
    unsigned a_base = smem_u32(As) + (unsigned)(((warp_m*32 + arow)*40 + acol) * 2);
    int lt = l & 15;
    unsigned b_base = smem_u32(Bs) + (unsigned)((lt*264 + warp_n*64) * 2);

    {
        *(uint4*)&As[a_row*40 + a_seg*8] =
            *(const uint4*)(g_h16 + (size_t)(m0+a_row)*(R_*D_) + a_seg*8);
        #pragma unroll
        for (int it=0; it<4; it++) {
            int rb = b_row + it*8;
            *(uint4*)&Bs[rb*264 + b_seg*8] =
                *(const uint4*)(g_wf16 + (size_t)rb*D_ + b_seg*8);
        }
    }
    __syncthreads();

    for (int c0 = 0; c0 < R_*D_; c0 += 32) {
        bool nxt = (c0 + 32 < R_*D_);
        uint4 pa0, pb[4];
        if (nxt) {
            pa0 = *(const uint4*)(g_h16 + (size_t)(m0+a_row)*(R_*D_) + c0+32 + a_seg*8);
            #pragma unroll
            for (int it=0; it<4; it++)
                pb[it] = *(const uint4*)(g_wf16 + (size_t)(c0+32+b_row+it*8)*D_ + b_seg*8);
        }
        #pragma unroll
        for (int ks = 0; ks < 2; ks++) {
            unsigned a0,a1,a2,a3;
            unsigned bfr[8][2];
            #pragma unroll
            for (int nt=0; nt<8; nt++) {
                unsigned addr = b_base + (unsigned)((ks*16*264 + nt*8) * 2);
                LDSM_X2T(bfr[nt][0], bfr[nt][1], addr);
            }
            #pragma unroll
            for (int mt=0; mt<2; mt++) {
                unsigned addr = a_base + (unsigned)((mt*16*40 + ks*16) * 2);
                LDSM_X4(a0,a1,a2,a3, addr);
                #pragma unroll
                for (int nt=0; nt<8; nt++)
                    MMA16816(acc[mt][nt], a0,a1,a2,a3, bfr[nt][0], bfr[nt][1]);
            }
        }
        __syncthreads();
        if (nxt) {
            *(uint4*)&As[a_row*40 + a_seg*8] = pa0;
            #pragma unroll
            for (int it=0; it<4; it++)
                *(uint4*)&Bs[(b_row+it*8)*264 + b_seg*8] = pb[it];
            __syncthreads();
        }
    }

    // epilogue: y = node_embed + relu(acc + bias); LN per row of 256
    #pragma unroll
    for (int mt=0; mt<2; mt++) {
        #pragma unroll
        for (int half=0; half<2; half++) {
            int row_l = warp_m*32 + mt*16 + quad + half*8;
            int grow = m0 + row_l;
            float s = 0.f, sq = 0.f;
            #pragma unroll
            for (int nt=0; nt<8; nt++) {
                int col = warp_n*64 + nt*8 + qlane*2;
                float2 bb = *(const float2*)(WF_b + col);
                float h0 = acc[mt][nt][half*2+0] + bb.x; h0 = h0 > 0.f ? h0 : 0.f;
                float h1 = acc[mt][nt][half*2+1] + bb.y; h1 = h1 > 0.f ? h1 : 0.f;
                float2 ne = *(const float2*)(node_embed + (size_t)grow*D_ + col);
                float y0 = ne.x + h0, y1 = ne.y + h1;
                acc[mt][nt][half*2+0] = y0;
                acc[mt][nt][half*2+1] = y1;
                s += y0 + y1;
                sq = fmaf(y0, y0, fmaf(y1, y1, sq));
            }
            s  += __shfl_xor_sync(0xffffffffu, s, 1);
            s  += __shfl_xor_sync(0xffffffffu, s, 2);
            sq += __shfl_xor_sync(0xffffffffu, sq, 1);
            sq += __shfl_xor_sync(0xffffffffu, sq, 2);
            if (qlane == 0) part[row_l][warp_n] = make_float2(s, sq);
        }
    }
    __syncthreads();
    #pragma unroll
    for (int mt=0; mt<2; mt++) {
        #pragma unroll
        for (int half=0; half<2; half++) {
            int row_l = warp_m*32 + mt*16 + quad + half*8;
            int grow = m0 + row_l;
            float s = 0.f, sq = 0.f;
            #pragma unroll
            for (int w=0; w<4; w++) { float2 pp = part[row_l][w]; s += pp.x; sq += pp.y; }
            float mu = s * (1.0f/256.0f);
            float var = sq * (1.0f/256.0f) - mu*mu;
            float rstd = rsqrtf(var + 1e-5f);
            #pragma unroll
            for (int nt=0; nt<8; nt++) {
                int col = warp_n*64 + nt*8 + qlane*2;
                float2 gg = *(const float2*)(ln_g + col);
                float2 bb = *(const float2*)(ln_b + col);
                float y0 = acc[mt][nt][half*2+0];
                float y1 = acc[mt][nt][half*2+1];
                float2 o;
                o.x = (y0 - mu) * rstd * gg.x + bb.x;
                o.y = (y1 - mu) * rstd * gg.y + bb.y;
                *(float2*)(out + (size_t)grow*D_ + col) = o;
            }
        }
    }
}

// ---------------- launch ----------------
extern "C" void kernel_launch(void* const* d_in, const int* in_sizes, int n_in,
                              void* d_out, int out_size) {
    const float* node_embed = (const float*)d_in[0];
    const float* input_x    = (const float*)d_in[1];
    const int*   adj        = (const int*)  d_in[2];
    const float* WQi_w      = (const float*)d_in[3];
    const float* WQi_b      = (const float*)d_in[4];
    const float* WQ_w       = (const float*)d_in[5];
    const float* WQ_b       = (const float*)d_in[6];
    const float* WK_w       = (const float*)d_in[7];
    const float* WK_b       = (const float*)d_in[8];
    const float* WV_w       = (const float*)d_in[9];
    const float* WV_b       = (const float*)d_in[10];
    const float* WF_w       = (const float*)d_in[11];
    const float* WF_b       = (const float*)d_in[12];
    const float* ln_g       = (const float*)d_in[13];
    const float* ln_b       = (const float*)d_in[14];
    float* out = (float*)d_out;

    k_x1      <<<B_, F_>>>(input_x, WQi_w, WQi_b);
    k_cat     <<<M_TOT, 192>>>(node_embed);
    k_cvtw    <<<1216, 256>>>(WQ_w, WK_w, WV_w, WF_w);
    k_qkv16   <<<dim3(10, 128), 256>>>(WQ_b, WK_b, WV_b);
    k_scores16<<<dim3(16, 16, B_*R_), 256>>>(adj);
    k_softmax <<<B_*R_*N_, 256>>>();
    k_av16    <<<dim3(2, 16, B_*R_), 256>>>();
    k_fused16 <<<M_TOT/64, 256>>>(node_embed, WF_b, ln_g, ln_b, out);
}

// round 5
// speedup vs baseline: 4.7577x; 1.0657x over previous
#include <cuda_runtime.h>
#include <cuda_bf16.h>
#include <math.h>

#define B_ 8
#define N_ 2048
#define D_ 256
#define F_ 128
#define R_ 2
#define KQ 384            // D_+F_
#define M_TOT (B_*N_)     // 16384
#define NWORD 64          // 2048/32

typedef __nv_bfloat16 bf16;
typedef __nv_bfloat162 bf162;

// ---------------- scratch ----------------
__device__ float g_x1[B_*F_];
__device__ bf16  g_cat[(size_t)M_TOT*KQ];
__device__ bf16  g_q16[(size_t)M_TOT*D_];
__device__ bf16  g_k16[(size_t)B_*R_*N_*D_];
__device__ bf16  g_v16[(size_t)B_*R_*N_*D_];
__device__ bf16  g_h16[(size_t)M_TOT*R_*D_];
__device__ unsigned g_mask[(size_t)B_*R_*NWORD*N_];     // [p][word][row] 8MB
__device__ bf16  g_wq16[KQ*D_];
__device__ bf16  g_wk16[R_*KQ*D_];
__device__ bf16  g_wv16[R_*KQ*D_];
__device__ bf16  g_wf16[R_*D_*D_];

// ---------------- PTX helpers ----------------
__device__ __forceinline__ unsigned smem_u32(const void* p) {
    return (unsigned)__cvta_generic_to_shared(p);
}
#define LDSM_X4(r0,r1,r2,r3,addr) \
    asm volatile("ldmatrix.sync.aligned.m8n8.x4.shared.b16 {%0,%1,%2,%3}, [%4];" \
        : "=r"(r0),"=r"(r1),"=r"(r2),"=r"(r3) : "r"(addr))
#define LDSM_X4T(r0,r1,r2,r3,addr) \
    asm volatile("ldmatrix.sync.aligned.m8n8.x4.trans.shared.b16 {%0,%1,%2,%3}, [%4];" \
        : "=r"(r0),"=r"(r1),"=r"(r2),"=r"(r3) : "r"(addr))
#define LDSM_X2T(r0,r1,addr) \
    asm volatile("ldmatrix.sync.aligned.m8n8.x2.trans.shared.b16 {%0,%1}, [%2];" \
        : "=r"(r0),"=r"(r1) : "r"(addr))
#define MMA16816(c,a0,a1,a2,a3,b0,b1) \
    asm volatile("mma.sync.aligned.m16n8k16.row.col.f32.bf16.bf16.f32 " \
        "{%0,%1,%2,%3},{%4,%5,%6,%7},{%8,%9},{%0,%1,%2,%3};" \
        : "+f"(c[0]),"+f"(c[1]),"+f"(c[2]),"+f"(c[3]) \
        : "r"(a0),"r"(a1),"r"(a2),"r"(a3),"r"(b0),"r"(b1))
#define CPA16(s,g) asm volatile("cp.async.cg.shared.global [%0], [%1], 16;" :: "r"(s), "l"(g))
#define CPA_COMMIT() asm volatile("cp.async.commit_group;" ::: "memory")
#define CPA_WAIT0() asm volatile("cp.async.wait_group 0;" ::: "memory")

static __device__ __forceinline__ unsigned pk2(float a, float b) {
    bf162 t = __float22bfloat162_rn(make_float2(a, b));
    return *(unsigned*)&t;
}

// ---------------- x1 ----------------
__global__ void k_x1(const float* __restrict__ input_x,
                     const float* __restrict__ Ww,
                     const float* __restrict__ Wb) {
    __shared__ float row[F_];
    int b = blockIdx.x, j = threadIdx.x;
    row[j] = input_x[b*F_ + j];
    __syncthreads();
    float s = Wb[j];
    #pragma unroll 4
    for (int c = 0; c < F_; c++) s = fmaf(row[c], Ww[c*F_ + j], s);
    g_x1[b*F_ + j] = s;
}

// ---------------- concat ----------------
__global__ void k_cat(const float* __restrict__ node_embed) {
    int row = blockIdx.x;
    int col2 = threadIdx.x * 2;
    float2 v;
    if (col2 < D_) v = *(const float2*)(node_embed + (size_t)row*D_ + col2);
    else           v = *(const float2*)(g_x1 + (size_t)(row >> 11)*F_ + (col2 - D_));
    *(bf162*)(g_cat + (size_t)row*KQ + col2) = __float22bfloat162_rn(v);
}

// ---------------- weights to bf16 ----------------
__global__ void k_cvtw(const float* __restrict__ wq, const float* __restrict__ wk,
                       const float* __restrict__ wv, const float* __restrict__ wf) {
    int i = blockIdx.x * blockDim.x + threadIdx.x;
    int e = i * 2;
    const int SQ = KQ*D_, SK = R_*KQ*D_, SF = R_*D_*D_;
    if (e < SQ) {
        *(bf162*)(g_wq16 + e) = __float22bfloat162_rn(*(const float2*)(wq + e));
    } else if (e < SQ + SK) {
        int o = e - SQ;
        *(bf162*)(g_wk16 + o) = __float22bfloat162_rn(*(const float2*)(wk + o));
    } else if (e < SQ + 2*SK) {
        int o = e - SQ - SK;
        *(bf162*)(g_wv16 + o) = __float22bfloat162_rn(*(const float2*)(wv + o));
    } else if (e < SQ + 2*SK + SF) {
        int o = e - SQ - 2*SK;
        *(bf162*)(g_wf16 + o) = __float22bfloat162_rn(*(const float2*)(wf + o));
    }
}

// ---------------- adj -> bitmask [p][word][row] ----------------
__global__ void k_adjmask(const int* __restrict__ adj) {
    int row = blockIdx.x, p = blockIdx.y;
    int tid = threadIdx.x;                 // 256
    int lane = tid & 31, warp = tid >> 5;
    const int* ap = adj + ((size_t)p*N_ + row)*N_;
    unsigned* mp = g_mask + (size_t)p*NWORD*N_;
    #pragma unroll
    for (int it = 0; it < 8; it++) {
        int idx = it*256 + tid;
        unsigned bits = __ballot_sync(0xffffffffu, ap[idx] != 0);
        if (lane == 0) mp[(size_t)(it*8 + warp)*N_ + row] = bits;
    }
}

// ============ qkv GEMM (mma.sync, proven) ============
__global__ void __launch_bounds__(256) k_qkv16(
        const float* __restrict__ WQ_b, const float* __restrict__ WK_b,
        const float* __restrict__ WV_b) {
    __shared__ bf16 As[128*40];
    __shared__ bf16 Bs[32*136];
    int tid = threadIdx.x;
    int l = tid & 31, warp = tid >> 5;
    int warp_m = warp & 1, warp_n = warp >> 1;
    int quad = l >> 2, qlane = l & 3;

    int bn = blockIdx.x;
    int m0 = blockIdx.y * 128;
    int chunk = bn >> 1;
    int j0 = (bn & 1) * 128;

    const bf16* Wg; const float* bias;
    if (chunk == 0)      { Wg = g_wq16;                           bias = WQ_b; }
    else if (chunk <= 2) { Wg = g_wk16 + (size_t)(chunk-1)*KQ*D_; bias = WK_b + (chunk-1)*D_; }
    else                 { Wg = g_wv16 + (size_t)(chunk-3)*KQ*D_; bias = WV_b + (chunk-3)*D_; }

    float acc[4][4][4];
    #pragma unroll
    for (int i=0;i<4;i++) for (int j=0;j<4;j++) for (int c=0;c<4;c++) acc[i][j][c]=0.f;

    int a_row = tid >> 2, a_seg = tid & 3;
    int b_row = tid >> 4, b_seg = tid & 15;

    int arow = (l & 7) + ((l >> 3) & 1) * 8;
    int acol = (l >> 4) * 8;
    unsigned a_base = smem_u32(As) + (unsigned)(((warp_m*64 + arow)*40 + acol) * 2);
    int lt = l & 15;
    unsigned b_base = smem_u32(Bs) + (unsigned)((lt*136 + warp_n*32) * 2);

    {
        #pragma unroll
        for (int it=0; it<2; it++) {
            int r = a_row + it*64;
            *(uint4*)&As[r*40 + a_seg*8] =
                *(const uint4*)(g_cat + (size_t)(m0+r)*KQ + a_seg*8);
            int rb = b_row + it*16;
            *(uint4*)&Bs[rb*136 + b_seg*8] =
                *(const uint4*)(Wg + (size_t)rb*D_ + j0 + b_seg*8);
        }
    }
    __syncthreads();

    for (int c0 = 0; c0 < KQ; c0 += 32) {
        bool nxt = (c0 + 32 < KQ);
        uint4 pa0,pa1,pb0,pb1;
        if (nxt) {
            pa0 = *(const uint4*)(g_cat + (size_t)(m0+a_row   )*KQ + c0+32 + a_seg*8);
            pa1 = *(const uint4*)(g_cat + (size_t)(m0+a_row+64)*KQ + c0+32 + a_seg*8);
            pb0 = *(const uint4*)(Wg + (size_t)(c0+32+b_row   )*D_ + j0 + b_seg*8);
            pb1 = *(const uint4*)(Wg + (size_t)(c0+32+b_row+16)*D_ + j0 + b_seg*8);
        }
        #pragma unroll
        for (int ks = 0; ks < 2; ks++) {
            unsigned a0,a1,a2,a3;
            unsigned bfr[4][2];
            #pragma unroll
            for (int nt=0; nt<4; nt++) {
                unsigned addr = b_base + (unsigned)((ks*16*136 + nt*8) * 2);
                LDSM_X2T(bfr[nt][0], bfr[nt][1], addr);
            }
            #pragma unroll
            for (int mt=0; mt<4; mt++) {
                unsigned addr = a_base + (unsigned)((mt*16*40 + ks*16) * 2);
                LDSM_X4(a0,a1,a2,a3, addr);
                #pragma unroll
                for (int nt=0; nt<4; nt++)
                    MMA16816(acc[mt][nt], a0,a1,a2,a3, bfr[nt][0], bfr[nt][1]);
            }
        }
        __syncthreads();
        if (nxt) {
            *(uint4*)&As[(a_row   )*40 + a_seg*8] = pa0;
            *(uint4*)&As[(a_row+64)*40 + a_seg*8] = pa1;
            *(uint4*)&Bs[(b_row   )*136 + b_seg*8] = pb0;
            *(uint4*)&Bs[(b_row+16)*136 + b_seg*8] = pb1;
            __syncthreads();
        }
    }

    #pragma unroll
    for (int mt=0; mt<4; mt++) {
        #pragma unroll
        for (int half=0; half<2; half++) {
            int i = m0 + warp_m*64 + mt*16 + quad + half*8;
            int bb = i >> 11, ntok = i & (N_-1);
            #pragma unroll
            for (int nt=0; nt<4; nt++) {
                int jj = j0 + warp_n*32 + nt*8 + qlane*2;
                float2 bv = *(const float2*)(bias + jj);
                float v0 = acc[mt][nt][half*2+0] + bv.x;
                float v1 = acc[mt][nt][half*2+1] + bv.y;
                bf16* dst;
                if (chunk == 0)      dst = g_q16 + (size_t)i*D_ + jj;
                else if (chunk <= 2) dst = g_k16 + ((size_t)(bb*R_ + (chunk-1))*N_ + ntok)*D_ + jj;
                else                 dst = g_v16 + ((size_t)(bb*R_ + (chunk-3))*N_ + ntok)*D_ + jj;
                *(bf162*)dst = __float22bfloat162_rn(make_float2(v0, v1));
            }
        }
    }
}

// ============ fused attention: O = softmax(mask(qk^T/16)) @ v ============
// 512 threads = 16 warps: wm = warp&7 (16 q-rows), wd = warp>>3 (kv-half for S, d-half for PV)
// smem: q[128][264] | K 2x[64][264] | V 2x[64][264] | P[128][72] | rs[2][128]
#define SM_Q   0
#define SM_K   67584
#define SM_V   135168
#define SM_P   202752
#define SM_RS  221184
#define SM_TOT 222208
#define NTILE  (N_/64)

__global__ void __launch_bounds__(512, 1) k_attn() {
    extern __shared__ char dsm[];
    unsigned sbase = smem_u32(dsm);
    int tid = threadIdx.x;
    int l = tid & 31, warp = tid >> 5;
    int wm = warp & 7, wd = warp >> 3;
    int quad = l >> 2, qlane = l & 3;

    int m0 = blockIdx.x * 128;
    int p  = blockIdx.y;

    const bf16* gq = g_q16 + ((size_t)(p >> 1)*N_ + m0)*D_;
    const bf16* gk = g_k16 + (size_t)p*N_*D_;
    const bf16* gv = g_v16 + (size_t)p*N_*D_;

    // ---- preload q (128x256) + tile 0 K,V ----
    {
        #pragma unroll
        for (int it = 0; it < 8; it++) {
            int c = it*512 + tid;          // 4096 chunks of 16B
            int row = c >> 5, seg = c & 31;
            CPA16(sbase + SM_Q + (unsigned)(row*528 + seg*16),
                  gq + (size_t)row*D_ + seg*8);
        }
        #pragma unroll
        for (int it = 0; it < 4; it++) {
            int c = it*512 + tid;          // 2048 chunks
            int row = c >> 5, seg = c & 31;
            CPA16(sbase + SM_K + (unsigned)(row*528 + seg*16),
                  gk + (size_t)row*D_ + seg*8);
            CPA16(sbase + SM_V + (unsigned)(row*528 + seg*16),
                  gv + (size_t)row*D_ + seg*8);
        }
        CPA_COMMIT();
    }

    float o[16][4];
    #pragma unroll
    for (int i=0;i<16;i++) { o[i][0]=0.f;o[i][1]=0.f;o[i][2]=0.f;o[i][3]=0.f; }
    float rs0 = 0.f, rs1 = 0.f;

    // frag base addresses
    unsigned qa = sbase + SM_Q +
        (unsigned)(((wm*16 + (l & 7) + ((l >> 3) & 1)*8)*264 + (l >> 4)*8) * 2);
    unsigned kb = (unsigned)(((wd*32 + (l & 7) + ((l >> 4) & 1)*8)*264 + ((l >> 3) & 1)*8) * 2);
    unsigned pa = sbase + SM_P +
        (unsigned)(((wm*16 + (l & 7) + ((l >> 3) & 1)*8)*72 + (l >> 4)*8) * 2);
    unsigned vb = (unsigned)(((l & 15)*264 + wd*128 + ((l >> 4) & 1)*8) * 2);

    bf16* Psm = (bf16*)(dsm + SM_P);
    float* rsm = (float*)(dsm + SM_RS);
    const unsigned* mbase = g_mask + (size_t)p*NWORD*N_ + m0 + wm*16;

    for (int t = 0; t < NTILE; t++) {
        int buf = t & 1;
        CPA_WAIT0();
        __syncthreads();
        if (t + 1 < NTILE) {
            const bf16* gk1 = gk + (size_t)(t+1)*64*D_;
            const bf16* gv1 = gv + (size_t)(t+1)*64*D_;
            unsigned kd = sbase + SM_K + (unsigned)((buf^1))*33792u;
            unsigned vd = sbase + SM_V + (unsigned)((buf^1))*33792u;
            #pragma unroll
            for (int it = 0; it < 4; it++) {
                int c = it*512 + tid;
                int row = c >> 5, seg = c & 31;
                CPA16(kd + (unsigned)(row*528 + seg*16), gk1 + (size_t)row*D_ + seg*8);
                CPA16(vd + (unsigned)(row*528 + seg*16), gv1 + (size_t)row*D_ + seg*8);
            }
            CPA_COMMIT();
        }

        // ---- S = q @ K^T for this warp's m16 x kv32 slice ----
        unsigned kbb = sbase + SM_K + (unsigned)buf*33792u + kb;
        float sc[4][4];
        #pragma unroll
        for (int i=0;i<4;i++){sc[i][0]=0.f;sc[i][1]=0.f;sc[i][2]=0.f;sc[i][3]=0.f;}
        #pragma unroll
        for (int ks = 0; ks < 16; ks++) {
            unsigned a0,a1,a2,a3;
            LDSM_X4(a0,a1,a2,a3, qa + (unsigned)(ks*32));
            #pragma unroll
            for (int nt16 = 0; nt16 < 2; nt16++) {
                unsigned b0,b1,b2,b3;
                LDSM_X4(b0,b1,b2,b3, kbb + (unsigned)((nt16*16*264 + ks*16) * 2));
                MMA16816(sc[nt16*2  ], a0,a1,a2,a3, b0,b1);
                MMA16816(sc[nt16*2+1], a0,a1,a2,a3, b2,b3);
            }
        }

        // ---- mask + exp + rowsum + P to smem ----
        {
            const unsigned* mw = mbase + (size_t)(t*2 + wd)*N_;
            unsigned w0 = mw[quad], w1 = mw[quad + 8];
            int r0 = wm*16 + quad;
            #pragma unroll
            for (int nt = 0; nt < 4; nt++) {
                int sh = nt*8 + qlane*2;
                float e00 = ((w0 >> sh) & 1u)     ? __expf(sc[nt][0]*0.0625f) : 0.f;
                float e01 = ((w0 >> (sh+1)) & 1u) ? __expf(sc[nt][1]*0.0625f) : 0.f;
                float e10 = ((w1 >> sh) & 1u)     ? __expf(sc[nt][2]*0.0625f) : 0.f;
                float e11 = ((w1 >> (sh+1)) & 1u) ? __expf(sc[nt][3]*0.0625f) : 0.f;
                rs0 += e00 + e01;
                rs1 += e10 + e11;
                int col = wd*32 + nt*8 + qlane*2;
                *(unsigned*)(Psm + r0*72 + col)       = pk2(e00, e01);
                *(unsigned*)(Psm + (r0+8)*72 + col)   = pk2(e10, e11);
            }
        }
        __syncthreads();

        // ---- O += P @ V (m16 x d128 for this warp, k = kv64) ----
        unsigned vbb = sbase + SM_V + (unsigned)buf*33792u + vb;
        #pragma unroll
        for (int ks2 = 0; ks2 < 4; ks2++) {
            unsigned a0,a1,a2,a3;
            LDSM_X4(a0,a1,a2,a3, pa + (unsigned)(ks2*32));
            #pragma unroll
            for (int nt16 = 0; nt16 < 8; nt16++) {
                unsigned b0,b1,b2,b3;
                LDSM_X4T(b0,b1,b2,b3, vbb + (unsigned)((ks2*16*264 + nt16*16) * 2));
                MMA16816(o[nt16*2  ], a0,a1,a2,a3, b0,b1);
                MMA16816(o[nt16*2+1], a0,a1,a2,a3, b2,b3);
            }
        }
    }

    // ---- rowsum reduce across qlane + wd halves ----
    rs0 += __shfl_xor_sync(0xffffffffu, rs0, 1);
    rs0 += __shfl_xor_sync(0xffffffffu, rs0, 2);
    rs1 += __shfl_xor_sync(0xffffffffu, rs1, 1);
    rs1 += __shfl_xor_sync(0xffffffffu, rs1, 2);
    if (qlane == 0) {
        rsm[wd*128 + wm*16 + quad]     = rs0;
        rsm[wd*128 + wm*16 + quad + 8] = rs1;
    }
    __syncthreads();
    int r0 = wm*16 + quad;
    float t0 = rsm[r0] + rsm[128 + r0];
    float t1 = rsm[r0 + 8] + rsm[128 + r0 + 8];
    float inv0 = t0 > 0.f ? __fdividef(1.f, t0) : 0.f;
    float inv1 = t1 > 0.f ? __fdividef(1.f, t1) : 0.f;

    // ---- write O/rsum to h_concat ----
    {
        bf16* d0 = g_h16 + ((size_t)((p >> 1)*N_ + m0 + r0))*(R_*D_) + (p & 1)*D_ + wd*128;
        bf16* d1 = d0 + (size_t)8*(R_*D_);
        #pragma unroll
        for (int nt = 0; nt < 16; nt++) {
            int col = nt*8 + qlane*2;
            *(unsigned*)(d0 + col) = pk2(o[nt][0]*inv0, o[nt][1]*inv0);
            *(unsigned*)(d1 + col) = pk2(o[nt][2]*inv1, o[nt][3]*inv1);
        }
    }
}

// ============ h_fused GEMM + relu + residual + LN (mma.sync, proven) ============
__global__ void __launch_bounds__(256) k_fused16(
        const float* __restrict__ node_embed,
        const float* __restrict__ WF_b,
        const float* __restrict__ ln_g, const float* __restrict__ ln_b,
        float* __restrict__ out) {
    __shared__ bf16 As[64*40];
    __shared__ bf16 Bs[32*264];
    __shared__ float2 part[64][4];
    int tid = threadIdx.x;
    int l = tid & 31, warp = tid >> 5;
    int warp_m = warp & 1, warp_n = warp >> 1;
    int quad = l >> 2, qlane = l & 3;
    int m0 = blockIdx.x * 64;

    float acc[2][8][4];
    #pragma unroll
    for (int i=0;i<2;i++) for (int j=0;j<8;j++) for (int c=0;c<4;c++) acc[i][j][c]=0.f;

    int a_row = tid >> 2, a_seg = tid & 3;
    int b_row = tid >> 5, b_seg = tid & 31;

    int arow = (l & 7) + ((l >> 3) & 1) * 8;
    int acol = (l >> 4) * 8;
    unsigned a_base = smem_u32(As) + (unsigned)(((warp_m*32 + arow)*40 + acol) * 2);
    int lt = l & 15;
    unsigned b_base = smem_u32(Bs) + (unsigned)((lt*264 + warp_n*64) * 2);

    {
        *(uint4*)&As[a_row*40 + a_seg*8] =
            *(const uint4*)(g_h16 + (size_t)(m0+a_row)*(R_*D_) + a_seg*8);
        #pragma unroll
        for (int it=0; it<4; it++) {
            int rb = b_row + it*8;
            *(uint4*)&Bs[rb*264 + b_seg*8] =
                *(const uint4*)(g_wf16 + (size_t)rb*D_ + b_seg*8);
        }
    }
    __syncthreads();

    for (int c0 = 0; c0 < R_*D_; c0 += 32) {
        bool nxt = (c0 + 32 < R_*D_);
        uint4 pa0, pb[4];
        if (nxt) {
            pa0 = *(const uint4*)(g_h16 + (size_t)(m0+a_row)*(R_*D_) + c0+32 + a_seg*8);
            #pragma unroll
            for (int it=0; it<4; it++)
                pb[it] = *(const uint4*)(g_wf16 + (size_t)(c0+32+b_row+it*8)*D_ + b_seg*8);
        }
        #pragma unroll
        for (int ks = 0; ks < 2; ks++) {
            unsigned a0,a1,a2,a3;
            unsigned bfr[8][2];
            #pragma unroll
            for (int nt=0; nt<8; nt++) {
                unsigned addr = b_base + (unsigned)((ks*16*264 + nt*8) * 2);
                LDSM_X2T(bfr[nt][0], bfr[nt][1], addr);
            }
            #pragma unroll
            for (int mt=0; mt<2; mt++) {
                unsigned addr = a_base + (unsigned)((mt*16*40 + ks*16) * 2);
                LDSM_X4(a0,a1,a2,a3, addr);
                #pragma unroll
                for (int nt=0; nt<8; nt++)
                    MMA16816(acc[mt][nt], a0,a1,a2,a3, bfr[nt][0], bfr[nt][1]);
            }
        }
        __syncthreads();
        if (nxt) {
            *(uint4*)&As[a_row*40 + a_seg*8] = pa0;
            #pragma unroll
            for (int it=0; it<4; it++)
                *(uint4*)&Bs[(b_row+it*8)*264 + b_seg*8] = pb[it];
            __syncthreads();
        }
    }

    #pragma unroll
    for (int mt=0; mt<2; mt++) {
        #pragma unroll
        for (int half=0; half<2; half++) {
            int row_l = warp_m*32 + mt*16 + quad + half*8;
            int grow = m0 + row_l;
            float s = 0.f, sq = 0.f;
            #pragma unroll
            for (int nt=0; nt<8; nt++) {
                int col = warp_n*64 + nt*8 + qlane*2;
                float2 bb = *(const float2*)(WF_b + col);
                float h0 = acc[mt][nt][half*2+0] + bb.x; h0 = h0 > 0.f ? h0 : 0.f;
                float h1 = acc[mt][nt][half*2+1] + bb.y; h1 = h1 > 0.f ? h1 : 0.f;
                float2 ne = *(const float2*)(node_embed + (size_t)grow*D_ + col);
                float y0 = ne.x + h0, y1 = ne.y + h1;
                acc[mt][nt][half*2+0] = y0;
                acc[mt][nt][half*2+1] = y1;
                s += y0 + y1;
                sq = fmaf(y0, y0, fmaf(y1, y1, sq));
            }
            s  += __shfl_xor_sync(0xffffffffu, s, 1);
            s  += __shfl_xor_sync(0xffffffffu, s, 2);
            sq += __shfl_xor_sync(0xffffffffu, sq, 1);
            sq += __shfl_xor_sync(0xffffffffu, sq, 2);
            if (qlane == 0) part[row_l][warp_n] = make_float2(s, sq);
        }
    }
    __syncthreads();
    #pragma unroll
    for (int mt=0; mt<2; mt++) {
        #pragma unroll
        for (int half=0; half<2; half++) {
            int row_l = warp_m*32 + mt*16 + quad + half*8;
            int grow = m0 + row_l;
            float s = 0.f, sq = 0.f;
            #pragma unroll
            for (int w=0; w<4; w++) { float2 pp = part[row_l][w]; s += pp.x; sq += pp.y; }
            float mu = s * (1.0f/256.0f);
            float var = sq * (1.0f/256.0f) - mu*mu;
            float rstd = rsqrtf(var + 1e-5f);
            #pragma unroll
            for (int nt=0; nt<8; nt++) {
                int col = warp_n*64 + nt*8 + qlane*2;
                float2 gg = *(const float2*)(ln_g + col);
                float2 bb = *(const float2*)(ln_b + col);
                float y0 = acc[mt][nt][half*2+0];
                float y1 = acc[mt][nt][half*2+1];
                float2 o;
                o.x = (y0 - mu) * rstd * gg.x + bb.x;
                o.y = (y1 - mu) * rstd * gg.y + bb.y;
                *(float2*)(out + (size_t)grow*D_ + col) = o;
            }
        }
    }
}

// ---------------- launch ----------------
extern "C" void kernel_launch(void* const* d_in, const int* in_sizes, int n_in,
                              void* d_out, int out_size) {
    const float* node_embed = (const float*)d_in[0];
    const float* input_x    = (const float*)d_in[1];
    const int*   adj        = (const int*)  d_in[2];
    const float* WQi_w      = (const float*)d_in[3];
    const float* WQi_b      = (const float*)d_in[4];
    const float* WQ_w       = (const float*)d_in[5];
    const float* WQ_b       = (const float*)d_in[6];
    const float* WK_w       = (const float*)d_in[7];
    const float* WK_b       = (const float*)d_in[8];
    const float* WV_w       = (const float*)d_in[9];
    const float* WV_b       = (const float*)d_in[10];
    const float* WF_w       = (const float*)d_in[11];
    const float* WF_b       = (const float*)d_in[12];
    const float* ln_g       = (const float*)d_in[13];
    const float* ln_b       = (const float*)d_in[14];
    float* out = (float*)d_out;

    cudaFuncSetAttribute(k_attn, cudaFuncAttributeMaxDynamicSharedMemorySize, SM_TOT);

    k_x1      <<<B_, F_>>>(input_x, WQi_w, WQi_b);
    k_cat     <<<M_TOT, 192>>>(node_embed);
    k_cvtw    <<<1216, 256>>>(WQ_w, WK_w, WV_w, WF_w);
    k_adjmask <<<dim3(N_, B_*R_), 256>>>(adj);
    k_qkv16   <<<dim3(10, 128), 256>>>(WQ_b, WK_b, WV_b);
    k_attn    <<<dim3(16, B_*R_), 512, SM_TOT>>>();
    k_fused16 <<<M_TOT/64, 256>>>(node_embed, WF_b, ln_g, ln_b, out);
}

// round 7
// speedup vs baseline: 4.9587x; 1.0422x over previous
#include <cuda_runtime.h>
#include <cuda_bf16.h>
#include <math.h>

#define B_ 8
#define N_ 2048
#define D_ 256
#define F_ 128
#define R_ 2
#define KQ 384            // D_+F_
#define M_TOT (B_*N_)     // 16384

typedef __nv_bfloat16 bf16;
typedef __nv_bfloat162 bf162;

// ---------------- scratch ----------------
__device__ float g_x1[B_*F_];
__device__ bf16  g_cat[(size_t)M_TOT*KQ];
__device__ bf16  g_q16[(size_t)M_TOT*D_];
__device__ bf16  g_k16[(size_t)B_*R_*N_*D_];
__device__ bf16  g_v16[(size_t)B_*R_*N_*D_];
__device__ bf16  g_h16[(size_t)M_TOT*R_*D_];
__device__ bf16  g_wq16[KQ*D_];
__device__ bf16  g_wk16[R_*KQ*D_];
__device__ bf16  g_wv16[R_*KQ*D_];
__device__ bf16  g_wf16[R_*D_*D_];

// ---------------- PTX helpers ----------------
__device__ __forceinline__ unsigned smem_u32(const void* p) {
    return (unsigned)__cvta_generic_to_shared(p);
}
#define LDSM_X4(r0,r1,r2,r3,addr) \
    asm volatile("ldmatrix.sync.aligned.m8n8.x4.shared.b16 {%0,%1,%2,%3}, [%4];" \
        : "=r"(r0),"=r"(r1),"=r"(r2),"=r"(r3) : "r"(addr))
#define LDSM_X4T(r0,r1,r2,r3,addr) \
    asm volatile("ldmatrix.sync.aligned.m8n8.x4.trans.shared.b16 {%0,%1,%2,%3}, [%4];" \
        : "=r"(r0),"=r"(r1),"=r"(r2),"=r"(r3) : "r"(addr))
#define LDSM_X2T(r0,r1,addr) \
    asm volatile("ldmatrix.sync.aligned.m8n8.x2.trans.shared.b16 {%0,%1}, [%2];" \
        : "=r"(r0),"=r"(r1) : "r"(addr))
#define MMA16816(c,a0,a1,a2,a3,b0,b1) \
    asm volatile("mma.sync.aligned.m16n8k16.row.col.f32.bf16.bf16.f32 " \
        "{%0,%1,%2,%3},{%4,%5,%6,%7},{%8,%9},{%0,%1,%2,%3};" \
        : "+f"(c[0]),"+f"(c[1]),"+f"(c[2]),"+f"(c[3]) \
        : "r"(a0),"r"(a1),"r"(a2),"r"(a3),"r"(b0),"r"(b1))
#define CPA16(s,g) asm volatile("cp.async.cg.shared.global [%0], [%1], 16;" :: "r"(s), "l"(g))
#define CPA_COMMIT() asm volatile("cp.async.commit_group;" ::: "memory")
#define CPA_WAIT0() asm volatile("cp.async.wait_group 0;" ::: "memory")

static __device__ __forceinline__ unsigned pk2(float a, float b) {
    bf162 t = __float22bfloat162_rn(make_float2(a, b));
    return *(unsigned*)&t;
}

// ---------------- x1 ----------------
__global__ void k_x1(const float* __restrict__ input_x,
                     const float* __restrict__ Ww,
                     const float* __restrict__ Wb) {
    __shared__ float row[F_];
    int b = blockIdx.x, j = threadIdx.x;
    row[j] = input_x[b*F_ + j];
    __syncthreads();
    float s = Wb[j];
    #pragma unroll 4
    for (int c = 0; c < F_; c++) s = fmaf(row[c], Ww[c*F_ + j], s);
    g_x1[b*F_ + j] = s;
}

// ---------------- concat ----------------
__global__ void k_cat(const float* __restrict__ node_embed) {
    int row = blockIdx.x;
    int col2 = threadIdx.x * 2;
    float2 v;
    if (col2 < D_) v = *(const float2*)(node_embed + (size_t)row*D_ + col2);
    else           v = *(const float2*)(g_x1 + (size_t)(row >> 11)*F_ + (col2 - D_));
    *(bf162*)(g_cat + (size_t)row*KQ + col2) = __float22bfloat162_rn(v);
}

// ---------------- weights to bf16 ----------------
__global__ void k_cvtw(const float* __restrict__ wq, const float* __restrict__ wk,
                       const float* __restrict__ wv, const float* __restrict__ wf) {
    int i = blockIdx.x * blockDim.x + threadIdx.x;
    int e = i * 2;
    const int SQ = KQ*D_, SK = R_*KQ*D_, SF = R_*D_*D_;
    if (e < SQ) {
        *(bf162*)(g_wq16 + e) = __float22bfloat162_rn(*(const float2*)(wq + e));
    } else if (e < SQ + SK) {
        int o = e - SQ;
        *(bf162*)(g_wk16 + o) = __float22bfloat162_rn(*(const float2*)(wk + o));
    } else if (e < SQ + 2*SK) {
        int o = e - SQ - SK;
        *(bf162*)(g_wv16 + o) = __float22bfloat162_rn(*(const float2*)(wv + o));
    } else if (e < SQ + 2*SK + SF) {
        int o = e - SQ - 2*SK;
        *(bf162*)(g_wf16 + o) = __float22bfloat162_rn(*(const float2*)(wf + o));
    }
}

// ============ qkv GEMM (mma.sync, proven) ============
__global__ void __launch_bounds__(256) k_qkv16(
        const float* __restrict__ WQ_b, const float* __restrict__ WK_b,
        const float* __restrict__ WV_b) {
    __shared__ bf16 As[128*40];
    __shared__ bf16 Bs[32*136];
    int tid = threadIdx.x;
    int l = tid & 31, warp = tid >> 5;
    int warp_m = warp & 1, warp_n = warp >> 1;
    int quad = l >> 2, qlane = l & 3;

    int bn = blockIdx.x;
    int m0 = blockIdx.y * 128;
    int chunk = bn >> 1;
    int j0 = (bn & 1) * 128;

    const bf16* Wg; const float* bias;
    if (chunk == 0)      { Wg = g_wq16;                           bias = WQ_b; }
    else if (chunk <= 2) { Wg = g_wk16 + (size_t)(chunk-1)*KQ*D_; bias = WK_b + (chunk-1)*D_; }
    else                 { Wg = g_wv16 + (size_t)(chunk-3)*KQ*D_; bias = WV_b + (chunk-3)*D_; }

    float acc[4][4][4];
    #pragma unroll
    for (int i=0;i<4;i++) for (int j=0;j<4;j++) for (int c=0;c<4;c++) acc[i][j][c]=0.f;

    int a_row = tid >> 2, a_seg = tid & 3;
    int b_row = tid >> 4, b_seg = tid & 15;

    int arow = (l & 7) + ((l >> 3) & 1) * 8;
    int acol = (l >> 4) * 8;
    unsigned a_base = smem_u32(As) + (unsigned)(((warp_m*64 + arow)*40 + acol) * 2);
    int lt = l & 15;
    unsigned b_base = smem_u32(Bs) + (unsigned)((lt*136 + warp_n*32) * 2);

    {
        #pragma unroll
        for (int it=0; it<2; it++) {
            int r = a_row + it*64;
            *(uint4*)&As[r*40 + a_seg*8] =
                *(const uint4*)(g_cat + (size_t)(m0+r)*KQ + a_seg*8);
            int rb = b_row + it*16;
            *(uint4*)&Bs[rb*136 + b_seg*8] =
                *(const uint4*)(Wg + (size_t)rb*D_ + j0 + b_seg*8);
        }
    }
    __syncthreads();

    for (int c0 = 0; c0 < KQ; c0 += 32) {
        bool nxt = (c0 + 32 < KQ);
        uint4 pa0,pa1,pb0,pb1;
        if (nxt) {
            pa0 = *(const uint4*)(g_cat + (size_t)(m0+a_row   )*KQ + c0+32 + a_seg*8);
            pa1 = *(const uint4*)(g_cat + (size_t)(m0+a_row+64)*KQ + c0+32 + a_seg*8);
            pb0 = *(const uint4*)(Wg + (size_t)(c0+32+b_row   )*D_ + j0 + b_seg*8);
            pb1 = *(const uint4*)(Wg + (size_t)(c0+32+b_row+16)*D_ + j0 + b_seg*8);
        }
        #pragma unroll
        for (int ks = 0; ks < 2; ks++) {
            unsigned a0,a1,a2,a3;
            unsigned bfr[4][2];
            #pragma unroll
            for (int nt=0; nt<4; nt++) {
                unsigned addr = b_base + (unsigned)((ks*16*136 + nt*8) * 2);
                LDSM_X2T(bfr[nt][0], bfr[nt][1], addr);
            }
            #pragma unroll
            for (int mt=0; mt<4; mt++) {
                unsigned addr = a_base + (unsigned)((mt*16*40 + ks*16) * 2);
                LDSM_X4(a0,a1,a2,a3, addr);
                #pragma unroll
                for (int nt=0; nt<4; nt++)
                    MMA16816(acc[mt][nt], a0,a1,a2,a3, bfr[nt][0], bfr[nt][1]);
            }
        }
        __syncthreads();
        if (nxt) {
            *(uint4*)&As[(a_row   )*40 + a_seg*8] = pa0;
            *(uint4*)&As[(a_row+64)*40 + a_seg*8] = pa1;
            *(uint4*)&Bs[(b_row   )*136 + b_seg*8] = pb0;
            *(uint4*)&Bs[(b_row+16)*136 + b_seg*8] = pb1;
            __syncthreads();
        }
    }

    #pragma unroll
    for (int mt=0; mt<4; mt++) {
        #pragma unroll
        for (int half=0; half<2; half++) {
            int i = m0 + warp_m*64 + mt*16 + quad + half*8;
            int bb = i >> 11, ntok = i & (N_-1);
            #pragma unroll
            for (int nt=0; nt<4; nt++) {
                int jj = j0 + warp_n*32 + nt*8 + qlane*2;
                float2 bv = *(const float2*)(bias + jj);
                float v0 = acc[mt][nt][half*2+0] + bv.x;
                float v1 = acc[mt][nt][half*2+1] + bv.y;
                bf16* dst;
                if (chunk == 0)      dst = g_q16 + (size_t)i*D_ + jj;
                else if (chunk <= 2) dst = g_k16 + ((size_t)(bb*R_ + (chunk-1))*N_ + ntok)*D_ + jj;
                else                 dst = g_v16 + ((size_t)(bb*R_ + (chunk-3))*N_ + ntok)*D_ + jj;
                *(bf162*)dst = __float22bfloat162_rn(make_float2(v0, v1));
            }
        }
    }
}

// ============ fused attention: O = softmax(mask(qk^T/16)) @ v, adj fused ============
// 512 threads = 16 warps.
// S phase:  wm = warp&7 (16 q-rows), wd = warp>>3 (kv-half of 32)
// PV phase: wp_m = warp&3 (32 q-rows), wp_d = warp>>2 (d-quarter of 64)
// smem: q[128][264] | K 2x[64][264] | V 2x[64][264] | P[128][72] | rs[2][128]
#define SM_Q   0
#define SM_K   67584
#define SM_V   135168
#define SM_P   202752
#define SM_RS  221184
#define SM_TOT 222208
#define NTILE  (N_/64)

__global__ void __launch_bounds__(512, 1) k_attn(const int* __restrict__ adj) {
    extern __shared__ char dsm[];
    unsigned sbase = smem_u32(dsm);
    int tid = threadIdx.x;
    int l = tid & 31, warp = tid >> 5;
    int wm = warp & 7, wd = warp >> 3;
    int wp_m = warp & 3, wp_d = warp >> 2;
    int quad = l >> 2, qlane = l & 3;

    int m0 = blockIdx.x * 128;
    int p  = blockIdx.y;

    const bf16* gq = g_q16 + ((size_t)(p >> 1)*N_ + m0)*D_;
    const bf16* gk = g_k16 + (size_t)p*N_*D_;
    const bf16* gv = g_v16 + (size_t)p*N_*D_;
    // adj rows for this warp's two 8-row groups, int2 granularity.
    // Base folds in wd*32 cols + qlane; per tile t stride = 64 ints = 32 int2.
    const int2* adj0 = (const int2*)(adj + ((size_t)p*N_ + m0 + wm*16 + quad    )*N_ + wd*32) + qlane;
    const int2* adj8 = (const int2*)(adj + ((size_t)p*N_ + m0 + wm*16 + quad + 8)*N_ + wd*32) + qlane;

    // ---- preload q (128x256) + tile 0 K,V ----
    {
        #pragma unroll
        for (int it = 0; it < 8; it++) {
            int c = it*512 + tid;
            int row = c >> 5, seg = c & 31;
            CPA16(sbase + SM_Q + (unsigned)(row*528 + seg*16),
                  gq + (size_t)row*D_ + seg*8);
        }
        #pragma unroll
        for (int it = 0; it < 4; it++) {
            int c = it*512 + tid;
            int row = c >> 5, seg = c & 31;
            CPA16(sbase + SM_K + (unsigned)(row*528 + seg*16),
                  gk + (size_t)row*D_ + seg*8);
            CPA16(sbase + SM_V + (unsigned)(row*528 + seg*16),
                  gv + (size_t)row*D_ + seg*8);
        }
        CPA_COMMIT();
    }

    float o[2][8][4];
    #pragma unroll
    for (int m=0;m<2;m++) for (int i=0;i<8;i++)
        { o[m][i][0]=0.f;o[m][i][1]=0.f;o[m][i][2]=0.f;o[m][i][3]=0.f; }
    float rs0 = 0.f, rs1 = 0.f;

    unsigned qa = sbase + SM_Q +
        (unsigned)(((wm*16 + (l & 7) + ((l >> 3) & 1)*8)*264 + (l >> 4)*8) * 2);
    unsigned kb = (unsigned)(((wd*32 + (l & 7) + ((l >> 4) & 1)*8)*264 + ((l >> 3) & 1)*8) * 2);
    unsigned pa = sbase + SM_P +
        (unsigned)(((wp_m*32 + (l & 7) + ((l >> 3) & 1)*8)*72 + (l >> 4)*8) * 2);
    unsigned vb = (unsigned)(((l & 15)*264 + wp_d*64 + ((l >> 4) & 1)*8) * 2);

    bf16* Psm = (bf16*)(dsm + SM_P);
    float* rsm = (float*)(dsm + SM_RS);

    for (int t = 0; t < NTILE; t++) {
        int buf = t & 1;
        CPA_WAIT0();
        __syncthreads();
        if (t + 1 < NTILE) {
            const bf16* gk1 = gk + (size_t)(t+1)*64*D_;
            const bf16* gv1 = gv + (size_t)(t+1)*64*D_;
            unsigned kd = sbase + SM_K + (unsigned)((buf^1))*33792u;
            unsigned vd = sbase + SM_V + (unsigned)((buf^1))*33792u;
            #pragma unroll
            for (int it = 0; it < 4; it++) {
                int c = it*512 + tid;
                int row = c >> 5, seg = c & 31;
                CPA16(kd + (unsigned)(row*528 + seg*16), gk1 + (size_t)row*D_ + seg*8);
                CPA16(vd + (unsigned)(row*528 + seg*16), gv1 + (size_t)row*D_ + seg*8);
            }
            CPA_COMMIT();
        }

        // ---- prefetch adj words for this tile (consumed after S MMAs) ----
        int2 am[8];
        #pragma unroll
        for (int nt = 0; nt < 4; nt++) {
            am[nt]     = adj0[t*32 + nt*4];
            am[4 + nt] = adj8[t*32 + nt*4];
        }

        // ---- S = q @ K^T for this warp's m16 x kv32 slice ----
        unsigned kbb = sbase + SM_K + (unsigned)buf*33792u + kb;
        float sc[4][4];
        #pragma unroll
        for (int i=0;i<4;i++){sc[i][0]=0.f;sc[i][1]=0.f;sc[i][2]=0.f;sc[i][3]=0.f;}
        #pragma unroll
        for (int ks = 0; ks < 16; ks++) {
            unsigned a0,a1,a2,a3;
            LDSM_X4(a0,a1,a2,a3, qa + (unsigned)(ks*32));
            #pragma unroll
            for (int nt16 = 0; nt16 < 2; nt16++) {
                unsigned b0,b1,b2,b3;
                LDSM_X4(b0,b1,b2,b3, kbb + (unsigned)((nt16*16*264 + ks*16) * 2));
                MMA16816(sc[nt16*2  ], a0,a1,a2,a3, b0,b1);
                MMA16816(sc[nt16*2+1], a0,a1,a2,a3, b2,b3);
            }
        }

        // ---- mask + exp + rowsum + P to smem ----
        {
            int r0 = wm*16 + quad;
            #pragma unroll
            for (int nt = 0; nt < 4; nt++) {
                float e00 = am[nt].x     ? __expf(sc[nt][0]*0.0625f) : 0.f;
                float e01 = am[nt].y     ? __expf(sc[nt][1]*0.0625f) : 0.f;
                float e10 = am[4+nt].x   ? __expf(sc[nt][2]*0.0625f) : 0.f;
                float e11 = am[4+nt].y   ? __expf(sc[nt][3]*0.0625f) : 0.f;
                rs0 += e00 + e01;
                rs1 += e10 + e11;
                int col = wd*32 + nt*8 + qlane*2;
                *(unsigned*)(Psm + r0*72 + col)     = pk2(e00, e01);
                *(unsigned*)(Psm + (r0+8)*72 + col) = pk2(e10, e11);
            }
        }
        __syncthreads();

        // ---- O += P @ V : warp slice m32 x d64, k = kv64 ----
        unsigned vbb = sbase + SM_V + (unsigned)buf*33792u + vb;
        #pragma unroll
        for (int ks2 = 0; ks2 < 4; ks2++) {
            unsigned b[4][4];
            #pragma unroll
            for (int nt16 = 0; nt16 < 4; nt16++)
                LDSM_X4T(b[nt16][0],b[nt16][1],b[nt16][2],b[nt16][3],
                         vbb + (unsigned)((ks2*16*264 + nt16*16) * 2));
            #pragma unroll
            for (int mt = 0; mt < 2; mt++) {
                unsigned a0,a1,a2,a3;
                LDSM_X4(a0,a1,a2,a3, pa + (unsigned)((mt*16*72 + ks2*16) * 2));
                #pragma unroll
                for (int nt16 = 0; nt16 < 4; nt16++) {
                    MMA16816(o[mt][nt16*2  ], a0,a1,a2,a3, b[nt16][0], b[nt16][1]);
                    MMA16816(o[mt][nt16*2+1], a0,a1,a2,a3, b[nt16][2], b[nt16][3]);
                }
            }
        }
    }

    // ---- rowsum reduce (S-phase indexing) ----
    rs0 += __shfl_xor_sync(0xffffffffu, rs0, 1);
    rs0 += __shfl_xor_sync(0xffffffffu, rs0, 2);
    rs1 += __shfl_xor_sync(0xffffffffu, rs1, 1);
    rs1 += __shfl_xor_sync(0xffffffffu, rs1, 2);
    if (qlane == 0) {
        rsm[wd*128 + wm*16 + quad]     = rs0;
        rsm[wd*128 + wm*16 + quad + 8] = rs1;
    }
    __syncthreads();

    // ---- normalize + write (PV indexing: rows wp_m*32.., cols wp_d*64..) ----
    #pragma unroll
    for (int mt = 0; mt < 2; mt++) {
        int r = wp_m*32 + mt*16 + quad;
        float ta = rsm[r]     + rsm[128 + r];
        float tb = rsm[r + 8] + rsm[128 + r + 8];
        float ia = ta > 0.f ? __fdividef(1.f, ta) : 0.f;
        float ib = tb > 0.f ? __fdividef(1.f, tb) : 0.f;
        bf16* d0 = g_h16 + ((size_t)((p >> 1)*N_ + m0 + r))*(R_*D_) + (p & 1)*D_ + wp_d*64;
        bf16* d1 = d0 + (size_t)8*(R_*D_);
        #pragma unroll
        for (int nt = 0; nt < 8; nt++) {
            int col = nt*8 + qlane*2;
            *(unsigned*)(d0 + col) = pk2(o[mt][nt][0]*ia, o[mt][nt][1]*ia);
            *(unsigned*)(d1 + col) = pk2(o[mt][nt][2]*ib, o[mt][nt][3]*ib);
        }
    }
}

// ============ h_fused GEMM + relu + residual + LN (mma.sync, proven) ============
__global__ void __launch_bounds__(256) k_fused16(
        const float* __restrict__ node_embed,
        const float* __restrict__ WF_b,
        const float* __restrict__ ln_g, const float* __restrict__ ln_b,
        float* __restrict__ out) {
    __shared__ bf16 As[64*40];
    __shared__ bf16 Bs[32*264];
    __shared__ float2 part[64][4];
    int tid = threadIdx.x;
    int l = tid & 31, warp = tid >> 5;
    int warp_m = warp & 1, warp_n = warp >> 1;
    int quad = l >> 2, qlane = l & 3;
    int m0 = blockIdx.x * 64;

    float acc[2][8][4];
    #pragma unroll
    for (int i=0;i<2;i++) for (int j=0;j<8;j++) for (int c=0;c<4;c++) acc[i][j][c]=0.f;

    int a_row = tid >> 2, a_seg = tid & 3;
    int b_row = tid >> 5, b_seg = tid & 31;

    int arow = (l & 7) + ((l >> 3) & 1) * 8;
    int acol = (l >> 4) * 8;
    unsigned a_base = smem_u32(As) + (unsigned)(((warp_m*32 + arow)*40 + acol) * 2);
    int lt = l & 15;
    unsigned b_base = smem_u32(Bs) + (unsigned)((lt*264 + warp_n*64) * 2);

    {
        *(uint4*)&As[a_row*40 + a_seg*8] =
            *(const uint4*)(g_h16 + (size_t)(m0+a_row)*(R_*D_) + a_seg*8);
        #pragma unroll
        for (int it=0; it<4; it++) {
            int rb = b_row + it*8;
            *(uint4*)&Bs[rb*264 + b_seg*8] =
                *(const uint4*)(g_wf16 + (size_t)rb*D_ + b_seg*8);
        }
    }
    __syncthreads();

    for (int c0 = 0; c0 < R_*D_; c0 += 32) {
        bool nxt = (c0 + 32 < R_*D_);
        uint4 pa0, pb[4];
        if (nxt) {
            pa0 = *(const uint4*)(g_h16 + (size_t)(m0+a_row)*(R_*D_) + c0+32 + a_seg*8);
            #pragma unroll
            for (int it=0; it<4; it++)
                pb[it] = *(const uint4*)(g_wf16 + (size_t)(c0+32+b_row+it*8)*D_ + b_seg*8);
        }
        #pragma unroll
        for (int ks = 0; ks < 2; ks++) {
            unsigned a0,a1,a2,a3;
            unsigned bfr[8][2];
            #pragma unroll
            for (int nt=0; nt<8; nt++) {
                unsigned addr = b_base + (unsigned)((ks*16*264 + nt*8) * 2);
                LDSM_X2T(bfr[nt][0], bfr[nt][1], addr);
            }
            #pragma unroll
            for (int mt=0; mt<2; mt++) {
                unsigned addr = a_base + (unsigned)((mt*16*40 + ks*16) * 2);
                LDSM_X4(a0,a1,a2,a3, addr);
                #pragma unroll
                for (int nt=0; nt<8; nt++)
                    MMA16816(acc[mt][nt], a0,a1,a2,a3, bfr[nt][0], bfr[nt][1]);
            }
        }
        __syncthreads();
        if (nxt) {
            *(uint4*)&As[a_row*40 + a_seg*8] = pa0;
            #pragma unroll
            for (int it=0; it<4; it++)
                *(uint4*)&Bs[(b_row+it*8)*264 + b_seg*8] = pb[it];
            __syncthreads();
        }
    }

    #pragma unroll
    for (int mt=0; mt<2; mt++) {
        #pragma unroll
        for (int half=0; half<2; half++) {
            int row_l = warp_m*32 + mt*16 + quad + half*8;
            int grow = m0 + row_l;
            float s = 0.f, sq = 0.f;
            #pragma unroll
            for (int nt=0; nt<8; nt++) {
                int col = warp_n*64 + nt*8 + qlane*2;
                float2 bb = *(const float2*)(WF_b + col);
                float h0 = acc[mt][nt][half*2+0] + bb.x; h0 = h0 > 0.f ? h0 : 0.f;
                float h1 = acc[mt][nt][half*2+1] + bb.y; h1 = h1 > 0.f ? h1 : 0.f;
                float2 ne = *(const float2*)(node_embed + (size_t)grow*D_ + col);
                float y0 = ne.x + h0, y1 = ne.y + h1;
                acc[mt][nt][half*2+0] = y0;
                acc[mt][nt][half*2+1] = y1;
                s += y0 + y1;
                sq = fmaf(y0, y0, fmaf(y1, y1, sq));
            }
            s  += __shfl_xor_sync(0xffffffffu, s, 1);
            s  += __shfl_xor_sync(0xffffffffu, s, 2);
            sq += __shfl_xor_sync(0xffffffffu, sq, 1);
            sq += __shfl_xor_sync(0xffffffffu, sq, 2);
            if (qlane == 0) part[row_l][warp_n] = make_float2(s, sq);
        }
    }
    __syncthreads();
    #pragma unroll
    for (int mt=0; mt<2; mt++) {
        #pragma unroll
        for (int half=0; half<2; half++) {
            int row_l = warp_m*32 + mt*16 + quad + half*8;
            int grow = m0 + row_l;
            float s = 0.f, sq = 0.f;
            #pragma unroll
            for (int w=0; w<4; w++) { float2 pp = part[row_l][w]; s += pp.x; sq += pp.y; }
            float mu = s * (1.0f/256.0f);
            float var = sq * (1.0f/256.0f) - mu*mu;
            float rstd = rsqrtf(var + 1e-5f);
            #pragma unroll
            for (int nt=0; nt<8; nt++) {
                int col = warp_n*64 + nt*8 + qlane*2;
                float2 gg = *(const float2*)(ln_g + col);
                float2 bb = *(const float2*)(ln_b + col);
                float y0 = acc[mt][nt][half*2+0];
                float y1 = acc[mt][nt][half*2+1];
                float2 o;
                o.x = (y0 - mu) * rstd * gg.x + bb.x;
                o.y = (y1 - mu) * rstd * gg.y + bb.y;
                *(float2*)(out + (size_t)grow*D_ + col) = o;
            }
        }
    }
}

// ---------------- launch ----------------
extern "C" void kernel_launch(void* const* d_in, const int* in_sizes, int n_in,
                              void* d_out, int out_size) {
    const float* node_embed = (const float*)d_in[0];
    const float* input_x    = (const float*)d_in[1];
    const int*   adj        = (const int*)  d_in[2];
    const float* WQi_w      = (const float*)d_in[3];
    const float* WQi_b      = (const float*)d_in[4];
    const float* WQ_w       = (const float*)d_in[5];
    const float* WQ_b       = (const float*)d_in[6];
    const float* WK_w       = (const float*)d_in[7];
    const float* WK_b       = (const float*)d_in[8];
    const float* WV_w       = (const float*)d_in[9];
    const float* WV_b       = (const float*)d_in[10];
    const float* WF_w       = (const float*)d_in[11];
    const float* WF_b       = (const float*)d_in[12];
    const float* ln_g       = (const float*)d_in[13];
    const float* ln_b       = (const float*)d_in[14];
    float* out = (float*)d_out;

    cudaFuncSetAttribute(k_attn, cudaFuncAttributeMaxDynamicSharedMemorySize, SM_TOT);

    k_x1      <<<B_, F_>>>(input_x, WQi_w, WQi_b);
    k_cat     <<<M_TOT, 192>>>(node_embed);
    k_cvtw    <<<1216, 256>>>(WQ_w, WK_w, WV_w, WF_w);
    k_qkv16   <<<dim3(10, 128), 256>>>(WQ_b, WK_b, WV_b);
    k_attn    <<<dim3(16, B_*R_), 512, SM_TOT>>>(adj);
    k_fused16 <<<M_TOT/64, 256>>>(node_embed, WF_b, ln_g, ln_b, out);
}